// round 11
// baseline (speedup 1.0000x reference)
#include <cuda_runtime.h>
#include <cuda_fp16.h>
#include <math.h>

#define Nn   262144
#define Ee   2097152
#define Bn   16
#define GXn  22
#define Gn   484
#define Sn   7744
#define EPSn 1e-5f
#define SXn  (16.0f/346.0f)
#define SYn  (12.0f/260.0f)
#define NCPY 64
#define MARKW ((Bn*Gn*Gn + 31)/32)

typedef unsigned long long ull;

// ---------------- scratch (statically zero-initialized; k_epi restores) -------
__device__ int      d_deg [Nn];        // self-restoring (hist + atomicSub)
__device__ int      d_rs  [Nn+1];
__device__ int      d_esrc[Ee];
__device__ float4   d_basF[Ee];
__device__ int      d_bsums[1024];
__device__ int      d_cid [Nn];
__device__ int      d_ccnt[Sn];        // epi-zeroed
__device__ float    d_pp  [Sn*2];      // epi-zeroed
__device__ unsigned d_xpe [Sn*32];     // epi-zeroed
__device__ __half   d_xph [Sn*32];
__device__ float    d_wv  [Sn];
__device__ unsigned d_markb[MARKW];    // epi-zeroed
__device__ int      d_EcD [1];         // epi-zeroed
__device__ int      d_csrc[Ee];
__device__ int      d_cdst[Ee];
__device__ int      d_degc[Sn];        // epi-zeroed
__device__ int      d_rsc [Sn+1];
__device__ int      d_curc[Sn+1];
__device__ int      d_esrcC[Ee];
__device__ float4   d_basFC[Ee];
__device__ unsigned d_mxD [1];         // epi-zeroed
__device__ float    d_twD [1];         // epi-zeroed
__device__ __half   d_H0 [(size_t)Nn*16];
__device__ __half   d_Ha [(size_t)Nn*32];
__device__ __half   d_Hb [(size_t)Nn*32];
__device__ __half   d_Hc [(size_t)Nn*32];
__device__ __half   d_Ch0[Sn*32];
__device__ __half   d_Ch1[Sn*32];
__device__ float    d_bnaccM[8][NCPY][128];   // epi-zeroed
__device__ float    d_ssbL[8][64];
__device__ int      d_tickS[2];        // epi-zeroed
__device__ int      d_tickL[8];        // epi-zeroed

// ---------------- helpers ----------------
__device__ __forceinline__ unsigned encf(float f){
    unsigned u = __float_as_uint(f);
    return (u & 0x80000000u) ? ~u : (u | 0x80000000u);
}
__device__ __forceinline__ float decf(unsigned u){
    return (u & 0x80000000u) ? __uint_as_float(u & 0x7FFFFFFFu) : __uint_as_float(~u);
}
// packed f32x2 ops (sm_10x FFMA2/FADD2 — only reachable via PTX)
__device__ __forceinline__ ull pk2(float lo, float hi){
    ull r;
    asm("mov.b64 %0, {%1, %2};" : "=l"(r) : "r"(__float_as_uint(lo)), "r"(__float_as_uint(hi)));
    return r;
}
__device__ __forceinline__ ull dup2(float v){ return pk2(v, v); }
__device__ __forceinline__ float2 upk2(ull p){
    unsigned lo, hi;
    asm("mov.b64 {%0, %1}, %2;" : "=r"(lo), "=r"(hi) : "l"(p));
    return make_float2(__uint_as_float(lo), __uint_as_float(hi));
}
__device__ __forceinline__ void ffma2(ull& acc, ull a, ull b){
    asm("fma.rn.f32x2 %0, %1, %2, %0;" : "+l"(acc) : "l"(a), "l"(b));
}
__device__ __forceinline__ void fadd2(ull& acc, ull a){
    asm("add.rn.f32x2 %0, %1, %0;" : "+l"(acc) : "l"(a));
}

// ---------------- prep: hist + cells + half-packed input ----------------
__global__ void k_prep(const int* __restrict__ dst, const float* __restrict__ pos,
                       const int* __restrict__ batch, const float* __restrict__ x){
    int e = blockIdx.x*blockDim.x + threadIdx.x;
    if (e < Ee) atomicAdd(&d_deg[dst[e]], 1);
    if (e < Nn){
        float px = pos[2*(size_t)e], py = pos[2*(size_t)e+1];
        int cx = min(max((int)floorf(px / SXn), 0), GXn-1);
        int cy = min(max((int)floorf(py / SYn), 0), GXn-1);
        int cid = batch[e]*Gn + cy*GXn + cx;
        d_cid[e] = cid;
        atomicAdd(&d_ccnt[cid], 1);
        atomicAdd(&d_pp[2*cid],   px);
        atomicAdd(&d_pp[2*cid+1], py);
        const float* xr = x + (size_t)e*10;
        __half* hr = d_H0 + (size_t)e*16;
        #pragma unroll
        for (int i=0;i<10;i++) hr[i] = __float2half(xr[i]);
        #pragma unroll
        for (int i=10;i<16;i++) hr[i] = __float2half(0.f);
    }
}

// ---------------- scan12: per-block prefix; last block scans sums -------------
__global__ void k_scan12(const int* __restrict__ in, int* __restrict__ out, int n,
                         int* __restrict__ tick){
    __shared__ int sh[1025];
    __shared__ int isLast;
    int t = threadIdx.x;
    int base = blockIdx.x*1024;
    int v = (base+t < n) ? in[base+t] : 0;
    sh[t] = v; __syncthreads();
    for (int off=1; off<1024; off<<=1){
        int a = (t>=off) ? sh[t-off] : 0;
        __syncthreads();
        sh[t] += a;
        __syncthreads();
    }
    if (base+t < n) out[base+t] = sh[t]-v;
    if (t==1023) d_bsums[blockIdx.x] = sh[1023];
    __threadfence();
    if (t==0) isLast = (atomicAdd(tick,1) == (int)gridDim.x-1);
    __syncthreads();
    if (!isLast) return;
    int nb = gridDim.x;
    int bv = (t<nb) ? __ldcg(&d_bsums[t]) : 0;
    __syncthreads();
    sh[t] = bv; __syncthreads();
    for (int off=1; off<1024; off<<=1){
        int a = (t>=off) ? sh[t-off] : 0;
        __syncthreads();
        sh[t] += a;
        __syncthreads();
    }
    if (t<=nb) d_bsums[t] = sh[t]-((t<nb)?bv:0);
}
__global__ void k_scan3(const int* __restrict__ in, int* __restrict__ out,
                        int* __restrict__ cur, int n){
    int i = blockIdx.x*blockDim.x + threadIdx.x;
    if (i >= n) return;
    int v = out[i] + d_bsums[i>>10];
    out[i] = v; cur[i] = v;
    if (i == n-1){ int tot = v + in[i]; out[n]=tot; cur[n]=tot; }
}

// scatter: src stream + float4 basis (no quantization)
__global__ void k_scatter(const int* __restrict__ src, const int* __restrict__ dst,
                          const float* __restrict__ ea){
    int e = blockIdx.x*blockDim.x + threadIdx.x;
    if (e >= Ee) return;
    float2 f = reinterpret_cast<const float2*>(ea)[e];
    float f0 = fminf(fmaxf(f.x, 0.f), 1.f);
    float f1 = fminf(fmaxf(f.y, 0.f), 1.f);
    int d = dst[e];
    int old = atomicSub(&d_deg[d], 1);
    int p = d_rs[d] + d_bsums[d>>10] + (old - 1);
    d_esrc[p] = src[e];
    d_basF[p] = make_float4((1.f-f0)*(1.f-f1), f0*(1.f-f1), (1.f-f0)*f1, f0*f1);
}

// ---------- BN stats tail ----------
__device__ __forceinline__ void bn_stats_tail(const float* g, const float* b,
                                              int layer, int cout, float denom, int useTw){
    __shared__ float part[2][128];
    __shared__ float tot[128];
    int t = threadIdx.x;
    int idx = t & 127, grp = t >> 7;
    float S = 0.f;
    for (int k = grp; k < NCPY; k += 2) S += __ldcg(&d_bnaccM[layer][k][idx]);
    part[grp][idx] = S;
    __syncthreads();
    if (t < 128) tot[t] = part[0][t] + part[1][t];
    __syncthreads();
    if (t < cout){
        float dn = useTw ? __ldcg(&d_twD[0]) : denom;
        float m = tot[t]/dn;
        float v = tot[64+t]/dn - m*m;
        float a = g[t]*rsqrtf(v + EPSn);
        d_ssbL[layer][t]    = a;
        d_ssbL[layer][32+t] = b[t] - m*a;
    }
}

// ---------------- fused fine layer (D=4 dsts/warp, f32x2 math) ----------------
template<int CINH, int COUT, bool RESID>
__global__ void k_fuse2(const __half* __restrict__ X1, const __half* __restrict__ X2,
                        const float* __restrict__ W, __half* __restrict__ uout,
                        const int* __restrict__ rs, const int* __restrict__ bs,
                        const int* __restrict__ esrc, const float4* __restrict__ basF,
                        int layer, int wcin, int ab1, int ab2,
                        const float* __restrict__ g, const float* __restrict__ bb_){
    constexpr int CPL  = CINH/8;
    constexpr int NOUT = COUT/8;
    __shared__ float Wsh[4*CINH*COUT];
    __shared__ float A1s[32], B1s[32], A2s[32];
    __shared__ float As[8][4][4][CINH];
    __shared__ float sv[8][32][NOUT];
    __shared__ int   isLast;
    int tid = threadIdx.x;
    for (int idx = tid; idx < 4*wcin*COUT; idx += 256) Wsh[idx] = W[idx];
    if (tid < 32){
        A1s[tid] = (ab1 >= 0) ? d_ssbL[ab1][tid]    : 1.f;
        float b1 = (ab1 >= 0) ? d_ssbL[ab1][32+tid] : 0.f;
        A2s[tid] = (ab2 >= 0) ? d_ssbL[ab2][tid]    : 0.f;
        float b2 = (ab2 >= 0) ? d_ssbL[ab2][32+tid] : 0.f;
        B1s[tid] = b1 + b2;
    }
    __syncthreads();
    int w = tid >> 5, lane = tid & 31;
    int sub = lane >> 3, il = lane & 7;
    int d = (blockIdx.x*8 + w)*4 + sub;
    int beg = rs[d]   + bs[d>>10];
    int end = rs[d+1] + bs[(d+1)>>10];

    ull A01[CPL], A23[CPL], E01[CPL], E23[CPL];
    ull K01 = 0ull, K23 = 0ull;
    #pragma unroll
    for (int cc=0;cc<CPL;cc++){ A01[cc]=0ull; A23[cc]=0ull; E01[cc]=0ull; E23[cc]=0ull; }
    const __half2* X1h = reinterpret_cast<const __half2*>(X1);
    const __half2* X2h = reinterpret_cast<const __half2*>(X2);

    #pragma unroll 2
    for (int p = beg; p < end; p++){
        float4 bq = __ldg(&basF[p]);
        ull b01 = pk2(bq.x, bq.y), b23 = pk2(bq.z, bq.w);
        fadd2(K01, b01); fadd2(K23, b23);
        int sa = esrc[p];
        if (CPL == 2){
            float2 xa = __half22float2(X1h[(size_t)sa*8 + il]);
            ull x0 = dup2(xa.x), x1 = dup2(xa.y);
            ffma2(A01[0], b01, x0); ffma2(A23[0], b23, x0);
            ffma2(A01[CPL-1], b01, x1); ffma2(A23[CPL-1], b23, x1);
            if (RESID){
                float2 ya = __half22float2(X2h[(size_t)sa*8 + il]);
                ull y0 = dup2(ya.x), y1 = dup2(ya.y);
                ffma2(E01[0], b01, y0); ffma2(E23[0], b23, y0);
                ffma2(E01[CPL-1], b01, y1); ffma2(E23[CPL-1], b23, y1);
            }
        } else {
            float xa = __half2float(X1[(size_t)sa*8 + il]);
            ull x0 = dup2(xa);
            ffma2(A01[0], b01, x0); ffma2(A23[0], b23, x0);
        }
    }

    // unpack + BN fold -> smem staging
    float2 k01 = upk2(K01), k23 = upk2(K23);
    float kv[4] = {k01.x, k01.y, k23.x, k23.y};
    #pragma unroll
    for (int cc=0;cc<CPL;cc++){
        int ch = il*CPL + cc;
        float2 a01 = upk2(A01[cc]), a23 = upk2(A23[cc]);
        float c0 = a01.x, c1 = a01.y, c2 = a23.x, c3 = a23.y;
        float e0 = 0.f, e1 = 0.f, e2 = 0.f, e3 = 0.f;
        if (RESID){
            float2 r01 = upk2(E01[cc]), r23 = upk2(E23[cc]);
            e0 = r01.x; e1 = r01.y; e2 = r23.x; e3 = r23.y;
        }
        float a1 = A1s[ch], a2 = A2s[ch], bbv = B1s[ch];
        As[w][sub][0][ch] = a1*c0 + a2*e0 + bbv*kv[0];
        As[w][sub][1][ch] = a1*c1 + a2*e1 + bbv*kv[1];
        As[w][sub][2][ch] = a1*c2 + a2*e2 + bbv*kv[2];
        As[w][sub][3][ch] = a1*c3 + a2*e3 + bbv*kv[3];
    }
    __syncwarp();
    int dg = end - beg; if (dg < 1) dg = 1;
    float inv = 1.f / (float)dg;
    #pragma unroll
    for (int q=0;q<NOUT;q++){
        int ch = (lane & 7) + 8*q;
        float v = 0.f;
        for (int k=0;k<4;k++){
            const float* ak = &As[w][sub][k][0];
            const float* wk = &Wsh[k*wcin*COUT + ch];
            for (int i=0;i<wcin;i++) v += ak[i] * wk[i*COUT];
        }
        v *= inv;
        v = (v > 0.f) ? v : expm1f(v);
        uout[(size_t)d*COUT + ch] = __float2half(v);
        sv[w][lane][q] = v;
    }
    __syncthreads();
    if (w == 0 && lane < COUT){
        float S = 0.f, Q = 0.f;
        int cl = lane & 7, q = lane >> 3;
        #pragma unroll
        for (int j=0;j<8;j++){
            #pragma unroll
            for (int s2=0;s2<4;s2++){
                float v = sv[j][s2*8 + cl][q];
                S += v; Q += v*v;
            }
        }
        int cp = blockIdx.x & (NCPY-1);
        atomicAdd(&d_bnaccM[layer][cp][lane],    S);
        atomicAdd(&d_bnaccM[layer][cp][64+lane], Q);
    }
    __threadfence();
    __syncthreads();
    if (tid == 0) isLast = (atomicAdd(&d_tickL[layer],1) == (int)gridDim.x-1);
    __syncthreads();
    if (isLast) bn_stats_tail(g, bb_, layer, COUT, (float)Nn, 0);
}

// ---------------- fused coarse layer: block per dst (f32x2 math) --------------
__global__ void k_fuseC(const __half* __restrict__ X1, const float* __restrict__ W,
                        __half* __restrict__ uout, const int* __restrict__ rs,
                        const int* __restrict__ esrc, const float4* __restrict__ basF,
                        int layer, int ab1,
                        const float* __restrict__ g, const float* __restrict__ bb_){
    __shared__ float Wsh[4*32*32];
    __shared__ float A1s[32], B1s[32];
    __shared__ float accS[8][4][32];
    __shared__ float sKS[8][4];
    __shared__ float Afin[4][32];
    __shared__ int   isLast;
    int d = blockIdx.x, tid = threadIdx.x;
    int w = tid >> 5, lane = tid & 31;
    for (int idx = tid; idx < 4096; idx += 256) Wsh[idx] = W[idx];
    if (tid < 32){
        A1s[tid] = (ab1 >= 0) ? d_ssbL[ab1][tid]    : 1.f;
        B1s[tid] = (ab1 >= 0) ? d_ssbL[ab1][32+tid] : 0.f;
    }
    __syncthreads();
    int beg = rs[d], end = rs[d+1];
    ull C01 = 0ull, C23 = 0ull, K01 = 0ull, K23 = 0ull;
    #pragma unroll 2
    for (int p = beg + w; p < end; p += 8){
        float4 bq = __ldg(&basF[p]);
        ull b01 = pk2(bq.x, bq.y), b23 = pk2(bq.z, bq.w);
        int s = esrc[p];
        float xv = __half2float(X1[(size_t)s*32 + lane]);
        ull xd = dup2(xv);
        ffma2(C01, b01, xd); ffma2(C23, b23, xd);
        fadd2(K01, b01); fadd2(K23, b23);
    }
    float2 c01 = upk2(C01), c23 = upk2(C23);
    float2 k01 = upk2(K01), k23 = upk2(K23);
    accS[w][0][lane]=c01.x; accS[w][1][lane]=c01.y; accS[w][2][lane]=c23.x; accS[w][3][lane]=c23.y;
    if (lane == 0){ sKS[w][0]=k01.x; sKS[w][1]=k01.y; sKS[w][2]=k23.x; sKS[w][3]=k23.y; }
    __syncthreads();
    if (tid < 128){
        int k = tid >> 5, i = tid & 31;
        float a = 0.f, sk = 0.f;
        #pragma unroll
        for (int j = 0; j < 8; j++){ a += accS[j][k][i]; sk += sKS[j][k]; }
        Afin[k][i] = A1s[i]*a + B1s[i]*sk;
    }
    __syncthreads();
    if (w == 0){
        float v = 0.f;
        #pragma unroll
        for (int k = 0; k < 4; k++)
            for (int i = 0; i < 32; i++)
                v += Afin[k][i] * Wsh[(k*32+i)*32 + lane];
        int dg = end - beg; if (dg < 1) dg = 1;
        v /= (float)dg;
        v = (v > 0.f) ? v : expm1f(v);
        uout[(size_t)d*32 + lane] = __float2half(v);
        float ww = d_wv[d];
        int cp = blockIdx.x & (NCPY-1);
        atomicAdd(&d_bnaccM[layer][cp][lane],    ww*v);
        atomicAdd(&d_bnaccM[layer][cp][64+lane], ww*v*v);
    }
    __threadfence();
    __syncthreads();
    if (tid == 0) isLast = (atomicAdd(&d_tickL[layer],1) == (int)gridDim.x-1);
    __syncthreads();
    if (isLast) bn_stats_tail(g, bb_, layer, 32, 0.f, 1);
}

// ---------------- pooling ----------------
__global__ void k_poolmax(const __half* __restrict__ u){
    int idx = blockIdx.x*blockDim.x + threadIdx.x;
    if (idx >= Nn*32) return;
    int n = idx >> 5, c = idx & 31;
    float v = __half2float(u[idx])*d_ssbL[5][c] + d_ssbL[5][32+c];
    atomicMax(&d_xpe[d_cid[n]*32 + c], encf(v));
}

__global__ void k_cellfin(){
    int idx = blockIdx.x*blockDim.x + threadIdx.x;
    if (idx >= Sn*32) return;
    int s = idx >> 5, c = idx & 31;
    int cnt = d_ccnt[s];
    if (c == 0){
        float inv = 1.f / (float)(cnt > 1 ? cnt : 1);
        d_pp[2*s]   *= inv;
        d_pp[2*s+1] *= inv;
        float w = (cnt > 0) ? 1.f : 0.f;
        d_wv[s] = w;
        if (cnt > 0) atomicAdd(&d_twD[0], 1.f);
    }
    d_xph[idx] = __float2half((cnt > 0) ? decf(d_xpe[idx]) : 0.f);
}

__global__ void k_cedges(const int* __restrict__ src, const int* __restrict__ dst){
    int e = blockIdx.x*blockDim.x + threadIdx.x;
    int cs = d_cid[src[e]], cd = d_cid[dst[e]];
    bool win = false;
    float m = 0.f;
    if (cs != cd){
        int b = cs / Gn;
        int key = b*Gn*Gn + (cs - b*Gn)*Gn + (cd - b*Gn);
        unsigned bit = 1u << (key & 31);
        unsigned old = atomicOr(&d_markb[key >> 5], bit);
        if (!(old & bit)){
            win = true;
            float cx = d_pp[2*cs]   - d_pp[2*cd];
            float cy = d_pp[2*cs+1] - d_pp[2*cd+1];
            m = fmaxf(fabsf(cx), fabsf(cy));
        }
    }
    unsigned wmask = __ballot_sync(0xFFFFFFFFu, win);
    float wm = m;
    #pragma unroll
    for (int o = 16; o; o >>= 1) wm = fmaxf(wm, __shfl_xor_sync(0xFFFFFFFFu, wm, o));
    int lane = threadIdx.x & 31;
    int nwin = __popc(wmask);
    int base = 0;
    if (lane == 0 && nwin){
        base = atomicAdd(&d_EcD[0], nwin);
        atomicMax(&d_mxD[0], __float_as_uint(wm));
    }
    base = __shfl_sync(0xFFFFFFFFu, base, 0);
    if (win){
        int i = base + __popc(wmask & ((1u << lane) - 1));
        d_csrc[i] = cs; d_cdst[i] = cd;
        atomicAdd(&d_degc[cd], 1);
    }
}

__global__ void k_scatterC(){
    int i = blockIdx.x*blockDim.x + threadIdx.x;
    if (i >= d_EcD[0]) return;
    int cs = d_csrc[i], cd = d_cdst[i];
    int p = atomicAdd(&d_curc[cd], 1);
    float mx = __uint_as_float(d_mxD[0]);
    float den = 2.f*mx + 1e-12f;
    float f0 = (d_pp[2*cs]   - d_pp[2*cd])   / den + 0.5f;
    float f1 = (d_pp[2*cs+1] - d_pp[2*cd+1]) / den + 0.5f;
    f0 = fminf(fmaxf(f0, 0.f), 1.f);
    f1 = fminf(fmaxf(f1, 0.f), 1.f);
    d_esrcC[p] = cs;
    d_basFC[p] = make_float4((1.f-f0)*(1.f-f1), f0*(1.f-f1), (1.f-f0)*f1, f0*f1);
}

// ---------------- final ----------------
__global__ void k_final(const __half* __restrict__ h, const float* __restrict__ fcW,
                        float* __restrict__ out){
    __shared__ float ss[8][33];
    __shared__ float sw8[8];
    __shared__ float gm[32];
    __shared__ float swv;
    int b = blockIdx.x;
    int lane = threadIdx.x & 31, w = threadIdx.x >> 5;
    float a7 = d_ssbL[7][lane], b7 = d_ssbL[7][32+lane];
    float acc = 0.f, accw = 0.f;
    for (int s = b*Gn + w; s < (b+1)*Gn; s += 8){
        float ww = d_wv[s];
        acc  += ww * (a7*__half2float(h[(size_t)s*32 + lane]) + b7);
        accw += ww;
    }
    ss[w][lane] = acc;
    if (lane == 0) sw8[w] = accw;
    __syncthreads();
    if (threadIdx.x < 32){
        float S = 0.f;
        #pragma unroll
        for (int j=0;j<8;j++) S += ss[j][threadIdx.x];
        gm[threadIdx.x] = S;
    }
    if (threadIdx.x == 0){
        float W = 0.f;
        #pragma unroll
        for (int j=0;j<8;j++) W += sw8[j];
        swv = W;
    }
    __syncthreads();
    if (threadIdx.x < 10){
        float o = 0.f;
        #pragma unroll
        for (int c=0;c<32;c++) o += (gm[c]/swv) * fcW[c*10 + threadIdx.x];
        out[b*10 + threadIdx.x] = o;
    }
}

// ---------------- epilogue: restore scratch to zero for next graph replay -----
__global__ void k_epi(){
    int i = blockIdx.x*blockDim.x + threadIdx.x;
    int st = gridDim.x*blockDim.x;
    for (int j=i; j<MARKW; j+=st) d_markb[j]=0u;
    for (int j=i; j<Sn;    j+=st){ d_ccnt[j]=0; d_degc[j]=0; }
    for (int j=i; j<Sn*2;  j+=st) d_pp[j]=0.f;
    for (int j=i; j<Sn*32; j+=st) d_xpe[j]=0u;
    float* bm = &d_bnaccM[0][0][0];
    for (int j=i; j<8*NCPY*128; j+=st) bm[j]=0.f;
    if (i < 2) d_tickS[i]=0;
    if (i < 8) d_tickL[i]=0;
    if (i==0){ d_EcD[0]=0; d_mxD[0]=0u; d_twD[0]=0.f; }
}

// ---------------- host ----------------
template <typename T>
static T* devptr(const void* sym){
    void* p = nullptr;
    cudaGetSymbolAddress(&p, sym);
    return (T*)p;
}

extern "C" void kernel_launch(void* const* d_in, const int* in_sizes, int n_in,
                              void* d_out, int out_size){
    const float* x     = (const float*)d_in[0];
    const float* pos   = (const float*)d_in[1];
    const int*   batch = (const int*)  d_in[2];
    const int*   ei    = (const int*)  d_in[3];
    const int*   src   = ei;
    const int*   dst   = ei + Ee;
    const float* ea    = (const float*)d_in[4];
    const float* fcW   = (const float*)d_in[29];
    float* out = (float*)d_out;

    __half* pH0  = devptr<__half>(d_H0);
    __half* pHa  = devptr<__half>(d_Ha);
    __half* pHb  = devptr<__half>(d_Hb);
    __half* pHc  = devptr<__half>(d_Hc);
    __half* pxph = devptr<__half>(d_xph);
    __half* pCh0 = devptr<__half>(d_Ch0);
    __half* pCh1 = devptr<__half>(d_Ch1);
    int*    pdeg  = devptr<int>(d_deg);
    int*    prs   = devptr<int>(d_rs);
    int*    pbs   = devptr<int>(d_bsums);
    int*    pes   = devptr<int>(d_esrc);
    float4* pbf   = devptr<float4>(d_basF);
    int*    pdegc = devptr<int>(d_degc);
    int*    prsc  = devptr<int>(d_rsc);
    int*    pcurc = devptr<int>(d_curc);
    int*    pesC  = devptr<int>(d_esrcC);
    float4* pbfC  = devptr<float4>(d_basFC);
    int*    ptick = devptr<int>(d_tickS);

    // prolog: 3 launches before first conv (ncu -s 5 lands on fuse_l0)
    k_prep<<<Ee/256,256>>>(dst, pos, batch, x);
    k_scan12<<<256,1024>>>(pdeg, prs, Nn, ptick);
    k_scatter<<<Ee/256,256>>>(src, dst, ea);

    // fine layers, fused BN stats; grid = Nn/32 (D=4, 8 warps)
    k_fuse2<16, 8,false><<<Nn/32,256>>>(pH0, nullptr, (const float*)d_in[5],  pHa, prs, pbs, pes, pbf, 0, 10, -1, -1, (const float*)d_in[6],  (const float*)d_in[7]);
    k_fuse2< 8,16,false><<<Nn/32,256>>>(pHa, nullptr, (const float*)d_in[8],  pHb, prs, pbs, pes, pbf, 1,  8,  0, -1, (const float*)d_in[9],  (const float*)d_in[10]);
    k_fuse2<16,16,false><<<Nn/32,256>>>(pHb, nullptr, (const float*)d_in[11], pHc, prs, pbs, pes, pbf, 2, 16,  1, -1, (const float*)d_in[12], (const float*)d_in[13]);
    k_fuse2<16,16,false><<<Nn/32,256>>>(pHc, nullptr, (const float*)d_in[14], pHa, prs, pbs, pes, pbf, 3, 16,  2, -1, (const float*)d_in[15], (const float*)d_in[16]);
    k_fuse2<16,16,false><<<Nn/32,256>>>(pHa, nullptr, (const float*)d_in[17], pHb, prs, pbs, pes, pbf, 4, 16,  3, -1, (const float*)d_in[18], (const float*)d_in[19]);
    k_fuse2<16,32,true ><<<Nn/32,256>>>(pHb, pHc,     (const float*)d_in[20], pHa, prs, pbs, pes, pbf, 5, 16,  4,  2, (const float*)d_in[21], (const float*)d_in[22]);

    // pooling + coarse graph build
    k_poolmax<<<(Nn*32)/256,256>>>(pHa);
    k_cellfin<<<(Sn*32+255)/256,256>>>();
    k_cedges<<<Ee/256,256>>>(src, dst);
    k_scan12<<<8,1024>>>(pdegc, prsc, Sn, ptick+1);
    k_scan3<<<(Sn+255)/256,256>>>(pdegc, prsc, pcurc, Sn);
    k_scatterC<<<Ee/256,256>>>();

    // coarse layers (weighted BN, fused stats)
    k_fuseC<<<Sn,256>>>(pxph, (const float*)d_in[23], pCh0, prsc, pesC, pbfC, 6, -1, (const float*)d_in[24], (const float*)d_in[25]);
    k_fuseC<<<Sn,256>>>(pCh0, (const float*)d_in[26], pCh1, prsc, pesC, pbfC, 7,  6, (const float*)d_in[27], (const float*)d_in[28]);

    k_final<<<Bn,256>>>(pCh1, fcW, out);

    // epilogue: restore zeroed scratch for the next replay
    k_epi<<<512,256>>>();
    (void)in_sizes; (void)n_in; (void)out_size;
}

// round 12
// speedup vs baseline: 1.4878x; 1.4878x over previous
#include <cuda_runtime.h>
#include <cuda_fp16.h>
#include <math.h>

#define Nn   262144
#define Ee   2097152
#define Bn   16
#define GXn  22
#define Gn   484
#define Sn   7744
#define EPSn 1e-5f
#define SXn  (16.0f/346.0f)
#define SYn  (12.0f/260.0f)
#define NCPY 64
#define MARKW ((Bn*Gn*Gn + 31)/32)

// ---------------- scratch (statically zero-initialized; k_epi restores) -------
__device__ int      d_deg [Nn];        // self-restoring (hist + atomicSub)
__device__ int      d_rs  [Nn+1];
__device__ int      d_esrc[Ee];
__device__ float4   d_basF[Ee];
__device__ int      d_bsums[1024];
__device__ int      d_cid [Nn];
__device__ int      d_ccnt[Sn];        // epi-zeroed
__device__ float    d_pp  [Sn*2];      // epi-zeroed
__device__ unsigned d_xpe [Sn*32];     // epi-zeroed
__device__ __half   d_xph [Sn*32];
__device__ float    d_wv  [Sn];
__device__ unsigned d_markb[MARKW];    // epi-zeroed
__device__ int      d_EcD [1];         // epi-zeroed
__device__ int      d_csrc[Ee];
__device__ int      d_cdst[Ee];
__device__ int      d_degc[Sn];        // epi-zeroed
__device__ int      d_rsc [Sn+1];
__device__ int      d_curc[Sn+1];
__device__ int      d_esrcC[Ee];
__device__ float4   d_basFC[Ee];
__device__ unsigned d_mxD [1];         // epi-zeroed
__device__ float    d_twD [1];         // epi-zeroed
__device__ __half   d_H0 [(size_t)Nn*16];
__device__ __half   d_Ha [(size_t)Nn*32];
__device__ __half   d_Hb [(size_t)Nn*32];
__device__ __half   d_Hc [(size_t)Nn*32];
__device__ __half   d_Ch0[Sn*32];
__device__ __half   d_Ch1[Sn*32];
__device__ float    d_bnaccM[8][NCPY][128];   // epi-zeroed
__device__ float    d_ssbL[8][64];
__device__ int      d_tickS[2];        // epi-zeroed
__device__ int      d_tickL[8];        // epi-zeroed

// ---------------- helpers ----------------
__device__ __forceinline__ unsigned encf(float f){
    unsigned u = __float_as_uint(f);
    return (u & 0x80000000u) ? ~u : (u | 0x80000000u);
}
__device__ __forceinline__ float decf(unsigned u){
    return (u & 0x80000000u) ? __uint_as_float(u & 0x7FFFFFFFu) : __uint_as_float(~u);
}

// ---------------- prep: hist + cells + half-packed input ----------------
__global__ void k_prep(const int* __restrict__ dst, const float* __restrict__ pos,
                       const int* __restrict__ batch, const float* __restrict__ x){
    int e = blockIdx.x*blockDim.x + threadIdx.x;
    if (e < Ee) atomicAdd(&d_deg[dst[e]], 1);
    if (e < Nn){
        float px = pos[2*(size_t)e], py = pos[2*(size_t)e+1];
        int cx = min(max((int)floorf(px / SXn), 0), GXn-1);
        int cy = min(max((int)floorf(py / SYn), 0), GXn-1);
        int cid = batch[e]*Gn + cy*GXn + cx;
        d_cid[e] = cid;
        atomicAdd(&d_ccnt[cid], 1);
        atomicAdd(&d_pp[2*cid],   px);
        atomicAdd(&d_pp[2*cid+1], py);
        const float* xr = x + (size_t)e*10;
        __half* hr = d_H0 + (size_t)e*16;
        #pragma unroll
        for (int i=0;i<10;i++) hr[i] = __float2half(xr[i]);
        #pragma unroll
        for (int i=10;i<16;i++) hr[i] = __float2half(0.f);
    }
}

// ---------------- scan12: per-block prefix; last block scans sums -------------
__global__ void k_scan12(const int* __restrict__ in, int* __restrict__ out, int n,
                         int* __restrict__ tick){
    __shared__ int sh[1025];
    __shared__ int isLast;
    int t = threadIdx.x;
    int base = blockIdx.x*1024;
    int v = (base+t < n) ? in[base+t] : 0;
    sh[t] = v; __syncthreads();
    for (int off=1; off<1024; off<<=1){
        int a = (t>=off) ? sh[t-off] : 0;
        __syncthreads();
        sh[t] += a;
        __syncthreads();
    }
    if (base+t < n) out[base+t] = sh[t]-v;
    if (t==1023) d_bsums[blockIdx.x] = sh[1023];
    __threadfence();
    if (t==0) isLast = (atomicAdd(tick,1) == (int)gridDim.x-1);
    __syncthreads();
    if (!isLast) return;
    int nb = gridDim.x;
    int bv = (t<nb) ? __ldcg(&d_bsums[t]) : 0;
    __syncthreads();
    sh[t] = bv; __syncthreads();
    for (int off=1; off<1024; off<<=1){
        int a = (t>=off) ? sh[t-off] : 0;
        __syncthreads();
        sh[t] += a;
        __syncthreads();
    }
    if (t<=nb) d_bsums[t] = sh[t]-((t<nb)?bv:0);
}
__global__ void k_scan3(const int* __restrict__ in, int* __restrict__ out,
                        int* __restrict__ cur, int n){
    int i = blockIdx.x*blockDim.x + threadIdx.x;
    if (i >= n) return;
    int v = out[i] + d_bsums[i>>10];
    out[i] = v; cur[i] = v;
    if (i == n-1){ int tot = v + in[i]; out[n]=tot; cur[n]=tot; }
}

// scatter: src stream + float4 basis (no quantization)
__global__ void k_scatter(const int* __restrict__ src, const int* __restrict__ dst,
                          const float* __restrict__ ea){
    int e = blockIdx.x*blockDim.x + threadIdx.x;
    if (e >= Ee) return;
    float2 f = reinterpret_cast<const float2*>(ea)[e];
    float f0 = fminf(fmaxf(f.x, 0.f), 1.f);
    float f1 = fminf(fmaxf(f.y, 0.f), 1.f);
    int d = dst[e];
    int old = atomicSub(&d_deg[d], 1);
    int p = d_rs[d] + d_bsums[d>>10] + (old - 1);
    d_esrc[p] = src[e];
    d_basF[p] = make_float4((1.f-f0)*(1.f-f1), f0*(1.f-f1), (1.f-f0)*f1, f0*f1);
}

// ---------- BN stats tail ----------
__device__ __forceinline__ void bn_stats_tail(const float* g, const float* b,
                                              int layer, int cout, float denom, int useTw){
    __shared__ float part[2][128];
    __shared__ float tot[128];
    int t = threadIdx.x;
    int idx = t & 127, grp = t >> 7;
    float S = 0.f;
    for (int k = grp; k < NCPY; k += 2) S += __ldcg(&d_bnaccM[layer][k][idx]);
    part[grp][idx] = S;
    __syncthreads();
    if (t < 128) tot[t] = part[0][t] + part[1][t];
    __syncthreads();
    if (t < cout){
        float dn = useTw ? __ldcg(&d_twD[0]) : denom;
        float m = tot[t]/dn;
        float v = tot[64+t]/dn - m*m;
        float a = g[t]*rsqrtf(v + EPSn);
        d_ssbL[layer][t]    = a;
        d_ssbL[layer][32+t] = b[t] - m*a;
    }
}

// ---------------- fused fine layer (D=4 dsts/warp, float4 basis, scalar FMA) --
template<int CINH, int COUT, bool RESID>
__global__ void k_fuse2(const __half* __restrict__ X1, const __half* __restrict__ X2,
                        const float* __restrict__ W, __half* __restrict__ uout,
                        const int* __restrict__ rs, const int* __restrict__ bs,
                        const int* __restrict__ esrc, const float4* __restrict__ basF,
                        int layer, int wcin, int ab1, int ab2,
                        const float* __restrict__ g, const float* __restrict__ bb_){
    constexpr int CPL  = CINH/8;
    constexpr int NOUT = COUT/8;
    __shared__ float Wsh[4*CINH*COUT];
    __shared__ float A1s[32], B1s[32], A2s[32];
    __shared__ float As[8][4][4][CINH];
    __shared__ float sv[8][32][NOUT];
    __shared__ int   isLast;
    int tid = threadIdx.x;
    for (int idx = tid; idx < 4*wcin*COUT; idx += 256) Wsh[idx] = W[idx];
    if (tid < 32){
        A1s[tid] = (ab1 >= 0) ? d_ssbL[ab1][tid]    : 1.f;
        float b1 = (ab1 >= 0) ? d_ssbL[ab1][32+tid] : 0.f;
        A2s[tid] = (ab2 >= 0) ? d_ssbL[ab2][tid]    : 0.f;
        float b2 = (ab2 >= 0) ? d_ssbL[ab2][32+tid] : 0.f;
        B1s[tid] = b1 + b2;
    }
    __syncthreads();
    int w = tid >> 5, lane = tid & 31;
    int sub = lane >> 3, il = lane & 7;
    int d = (blockIdx.x*8 + w)*4 + sub;
    int beg = rs[d]   + bs[d>>1024==0 ? (d>>10) : (d>>10)];   // placeholder avoided below
    beg = rs[d] + bs[d>>10];
    int end = rs[d+1] + bs[(d+1)>>10];

    float c[4][CPL]; float er[4][CPL];
    float k0=0.f,k1=0.f,k2=0.f,k3=0.f;
    #pragma unroll
    for (int k=0;k<4;k++)
        #pragma unroll
        for (int cc=0;cc<CPL;cc++){ c[k][cc]=0.f; er[k][cc]=0.f; }
    const __half2* X1h = reinterpret_cast<const __half2*>(X1);
    const __half2* X2h = reinterpret_cast<const __half2*>(X2);

    #pragma unroll 2
    for (int p = beg; p < end; p++){
        float4 bq = __ldg(&basF[p]);
        int sa = esrc[p];
        k0 += bq.x; k1 += bq.y; k2 += bq.z; k3 += bq.w;
        if (CPL == 2){
            float2 xa = __half22float2(X1h[(size_t)sa*8 + il]);
            c[0][0] += bq.x*xa.x; c[0][CPL-1] += bq.x*xa.y;
            c[1][0] += bq.y*xa.x; c[1][CPL-1] += bq.y*xa.y;
            c[2][0] += bq.z*xa.x; c[2][CPL-1] += bq.z*xa.y;
            c[3][0] += bq.w*xa.x; c[3][CPL-1] += bq.w*xa.y;
            if (RESID){
                float2 ya = __half22float2(X2h[(size_t)sa*8 + il]);
                er[0][0] += bq.x*ya.x; er[0][CPL-1] += bq.x*ya.y;
                er[1][0] += bq.y*ya.x; er[1][CPL-1] += bq.y*ya.y;
                er[2][0] += bq.z*ya.x; er[2][CPL-1] += bq.z*ya.y;
                er[3][0] += bq.w*ya.x; er[3][CPL-1] += bq.w*ya.y;
            }
        } else {
            float xa = __half2float(X1[(size_t)sa*8 + il]);
            c[0][0] += bq.x*xa; c[1][0] += bq.y*xa;
            c[2][0] += bq.z*xa; c[3][0] += bq.w*xa;
        }
    }

    float kv[4] = {k0, k1, k2, k3};
    #pragma unroll
    for (int cc=0;cc<CPL;cc++){
        int ch = il*CPL + cc;
        float a1 = A1s[ch], a2 = A2s[ch], bbv = B1s[ch];
        #pragma unroll
        for (int k=0;k<4;k++){
            float a = a1*c[k][cc] + bbv*kv[k];
            if (RESID) a += a2*er[k][cc];
            As[w][sub][k][ch] = a;
        }
    }
    __syncwarp();
    int dg = end - beg; if (dg < 1) dg = 1;
    float inv = 1.f / (float)dg;
    #pragma unroll
    for (int q=0;q<NOUT;q++){
        int ch = (lane & 7) + 8*q;
        float v = 0.f;
        for (int k=0;k<4;k++){
            const float* ak = &As[w][sub][k][0];
            const float* wk = &Wsh[k*wcin*COUT + ch];
            for (int i=0;i<wcin;i++) v += ak[i] * wk[i*COUT];
        }
        v *= inv;
        v = (v > 0.f) ? v : expm1f(v);
        uout[(size_t)d*COUT + ch] = __float2half(v);
        sv[w][lane][q] = v;
    }
    __syncthreads();
    if (w == 0 && lane < COUT){
        float S = 0.f, Q = 0.f;
        int cl = lane & 7, q = lane >> 3;
        #pragma unroll
        for (int j=0;j<8;j++){
            #pragma unroll
            for (int s2=0;s2<4;s2++){
                float v = sv[j][s2*8 + cl][q];
                S += v; Q += v*v;
            }
        }
        int cp = blockIdx.x & (NCPY-1);
        atomicAdd(&d_bnaccM[layer][cp][lane],    S);
        atomicAdd(&d_bnaccM[layer][cp][64+lane], Q);
    }
    __threadfence();
    __syncthreads();
    if (tid == 0) isLast = (atomicAdd(&d_tickL[layer],1) == (int)gridDim.x-1);
    __syncthreads();
    if (isLast) bn_stats_tail(g, bb_, layer, COUT, (float)Nn, 0);
}

// ---------------- fused coarse layer: block per dst (float4 basis) ------------
__global__ void k_fuseC(const __half* __restrict__ X1, const float* __restrict__ W,
                        __half* __restrict__ uout, const int* __restrict__ rs,
                        const int* __restrict__ esrc, const float4* __restrict__ basF,
                        int layer, int ab1,
                        const float* __restrict__ g, const float* __restrict__ bb_){
    __shared__ float Wsh[4*32*32];
    __shared__ float A1s[32], B1s[32];
    __shared__ float accS[8][4][32];
    __shared__ float sKS[8][4];
    __shared__ float Afin[4][32];
    __shared__ int   isLast;
    int d = blockIdx.x, tid = threadIdx.x;
    int w = tid >> 5, lane = tid & 31;
    for (int idx = tid; idx < 4096; idx += 256) Wsh[idx] = W[idx];
    if (tid < 32){
        A1s[tid] = (ab1 >= 0) ? d_ssbL[ab1][tid]    : 1.f;
        B1s[tid] = (ab1 >= 0) ? d_ssbL[ab1][32+tid] : 0.f;
    }
    __syncthreads();
    int beg = rs[d], end = rs[d+1];
    float c0=0,c1=0,c2=0,c3=0, k0=0,k1=0,k2=0,k3=0;
    #pragma unroll 2
    for (int p = beg + w; p < end; p += 8){
        float4 bq = __ldg(&basF[p]);
        int s = esrc[p];
        float xv = __half2float(X1[(size_t)s*32 + lane]);
        c0 += bq.x*xv; c1 += bq.y*xv; c2 += bq.z*xv; c3 += bq.w*xv;
        k0 += bq.x; k1 += bq.y; k2 += bq.z; k3 += bq.w;
    }
    accS[w][0][lane]=c0; accS[w][1][lane]=c1; accS[w][2][lane]=c2; accS[w][3][lane]=c3;
    if (lane == 0){ sKS[w][0]=k0; sKS[w][1]=k1; sKS[w][2]=k2; sKS[w][3]=k3; }
    __syncthreads();
    if (tid < 128){
        int k = tid >> 5, i = tid & 31;
        float a = 0.f, sk = 0.f;
        #pragma unroll
        for (int j = 0; j < 8; j++){ a += accS[j][k][i]; sk += sKS[j][k]; }
        Afin[k][i] = A1s[i]*a + B1s[i]*sk;
    }
    __syncthreads();
    if (w == 0){
        float v = 0.f;
        #pragma unroll
        for (int k = 0; k < 4; k++)
            for (int i = 0; i < 32; i++)
                v += Afin[k][i] * Wsh[(k*32+i)*32 + lane];
        int dg = end - beg; if (dg < 1) dg = 1;
        v /= (float)dg;
        v = (v > 0.f) ? v : expm1f(v);
        uout[(size_t)d*32 + lane] = __float2half(v);
        float ww = d_wv[d];
        int cp = blockIdx.x & (NCPY-1);
        atomicAdd(&d_bnaccM[layer][cp][lane],    ww*v);
        atomicAdd(&d_bnaccM[layer][cp][64+lane], ww*v*v);
    }
    __threadfence();
    __syncthreads();
    if (tid == 0) isLast = (atomicAdd(&d_tickL[layer],1) == (int)gridDim.x-1);
    __syncthreads();
    if (isLast) bn_stats_tail(g, bb_, layer, 32, 0.f, 1);
}

// ---------------- pooling ----------------
__global__ void k_poolmax(const __half* __restrict__ u){
    int idx = blockIdx.x*blockDim.x + threadIdx.x;
    if (idx >= Nn*32) return;
    int n = idx >> 5, c = idx & 31;
    float v = __half2float(u[idx])*d_ssbL[5][c] + d_ssbL[5][32+c];
    atomicMax(&d_xpe[d_cid[n]*32 + c], encf(v));
}

__global__ void k_cellfin(){
    int idx = blockIdx.x*blockDim.x + threadIdx.x;
    if (idx >= Sn*32) return;
    int s = idx >> 5, c = idx & 31;
    int cnt = d_ccnt[s];
    if (c == 0){
        float inv = 1.f / (float)(cnt > 1 ? cnt : 1);
        d_pp[2*s]   *= inv;
        d_pp[2*s+1] *= inv;
        float w = (cnt > 0) ? 1.f : 0.f;
        d_wv[s] = w;
        if (cnt > 0) atomicAdd(&d_twD[0], 1.f);
    }
    d_xph[idx] = __float2half((cnt > 0) ? decf(d_xpe[idx]) : 0.f);
}

__global__ void k_cedges(const int* __restrict__ src, const int* __restrict__ dst){
    int e = blockIdx.x*blockDim.x + threadIdx.x;
    int cs = d_cid[src[e]], cd = d_cid[dst[e]];
    bool win = false;
    float m = 0.f;
    if (cs != cd){
        int b = cs / Gn;
        int key = b*Gn*Gn + (cs - b*Gn)*Gn + (cd - b*Gn);
        unsigned bit = 1u << (key & 31);
        unsigned old = atomicOr(&d_markb[key >> 5], bit);
        if (!(old & bit)){
            win = true;
            float cx = d_pp[2*cs]   - d_pp[2*cd];
            float cy = d_pp[2*cs+1] - d_pp[2*cd+1];
            m = fmaxf(fabsf(cx), fabsf(cy));
        }
    }
    unsigned wmask = __ballot_sync(0xFFFFFFFFu, win);
    float wm = m;
    #pragma unroll
    for (int o = 16; o; o >>= 1) wm = fmaxf(wm, __shfl_xor_sync(0xFFFFFFFFu, wm, o));
    int lane = threadIdx.x & 31;
    int nwin = __popc(wmask);
    int base = 0;
    if (lane == 0 && nwin){
        base = atomicAdd(&d_EcD[0], nwin);
        atomicMax(&d_mxD[0], __float_as_uint(wm));
    }
    base = __shfl_sync(0xFFFFFFFFu, base, 0);
    if (win){
        int i = base + __popc(wmask & ((1u << lane) - 1));
        d_csrc[i] = cs; d_cdst[i] = cd;
        atomicAdd(&d_degc[cd], 1);
    }
}

__global__ void k_scatterC(){
    int i = blockIdx.x*blockDim.x + threadIdx.x;
    if (i >= d_EcD[0]) return;
    int cs = d_csrc[i], cd = d_cdst[i];
    int p = atomicAdd(&d_curc[cd], 1);
    float mx = __uint_as_float(d_mxD[0]);
    float den = 2.f*mx + 1e-12f;
    float f0 = (d_pp[2*cs]   - d_pp[2*cd])   / den + 0.5f;
    float f1 = (d_pp[2*cs+1] - d_pp[2*cd+1]) / den + 0.5f;
    f0 = fminf(fmaxf(f0, 0.f), 1.f);
    f1 = fminf(fmaxf(f1, 0.f), 1.f);
    d_esrcC[p] = cs;
    d_basFC[p] = make_float4((1.f-f0)*(1.f-f1), f0*(1.f-f1), (1.f-f0)*f1, f0*f1);
}

// ---------------- final ----------------
__global__ void k_final(const __half* __restrict__ h, const float* __restrict__ fcW,
                        float* __restrict__ out){
    __shared__ float ss[8][33];
    __shared__ float sw8[8];
    __shared__ float gm[32];
    __shared__ float swv;
    int b = blockIdx.x;
    int lane = threadIdx.x & 31, w = threadIdx.x >> 5;
    float a7 = d_ssbL[7][lane], b7 = d_ssbL[7][32+lane];
    float acc = 0.f, accw = 0.f;
    for (int s = b*Gn + w; s < (b+1)*Gn; s += 8){
        float ww = d_wv[s];
        acc  += ww * (a7*__half2float(h[(size_t)s*32 + lane]) + b7);
        accw += ww;
    }
    ss[w][lane] = acc;
    if (lane == 0) sw8[w] = accw;
    __syncthreads();
    if (threadIdx.x < 32){
        float S = 0.f;
        #pragma unroll
        for (int j=0;j<8;j++) S += ss[j][threadIdx.x];
        gm[threadIdx.x] = S;
    }
    if (threadIdx.x == 0){
        float W = 0.f;
        #pragma unroll
        for (int j=0;j<8;j++) W += sw8[j];
        swv = W;
    }
    __syncthreads();
    if (threadIdx.x < 10){
        float o = 0.f;
        #pragma unroll
        for (int c=0;c<32;c++) o += (gm[c]/swv) * fcW[c*10 + threadIdx.x];
        out[b*10 + threadIdx.x] = o;
    }
}

// ---------------- epilogue: restore scratch to zero for next graph replay -----
__global__ void k_epi(){
    int i = blockIdx.x*blockDim.x + threadIdx.x;
    int st = gridDim.x*blockDim.x;
    for (int j=i; j<MARKW; j+=st) d_markb[j]=0u;
    for (int j=i; j<Sn;    j+=st){ d_ccnt[j]=0; d_degc[j]=0; }
    for (int j=i; j<Sn*2;  j+=st) d_pp[j]=0.f;
    for (int j=i; j<Sn*32; j+=st) d_xpe[j]=0u;
    float* bm = &d_bnaccM[0][0][0];
    for (int j=i; j<8*NCPY*128; j+=st) bm[j]=0.f;
    if (i < 2) d_tickS[i]=0;
    if (i < 8) d_tickL[i]=0;
    if (i==0){ d_EcD[0]=0; d_mxD[0]=0u; d_twD[0]=0.f; }
}

// ---------------- host ----------------
template <typename T>
static T* devptr(const void* sym){
    void* p = nullptr;
    cudaGetSymbolAddress(&p, sym);
    return (T*)p;
}

extern "C" void kernel_launch(void* const* d_in, const int* in_sizes, int n_in,
                              void* d_out, int out_size){
    const float* x     = (const float*)d_in[0];
    const float* pos   = (const float*)d_in[1];
    const int*   batch = (const int*)  d_in[2];
    const int*   ei    = (const int*)  d_in[3];
    const int*   src   = ei;
    const int*   dst   = ei + Ee;
    const float* ea    = (const float*)d_in[4];
    const float* fcW   = (const float*)d_in[29];
    float* out = (float*)d_out;

    __half* pH0  = devptr<__half>(d_H0);
    __half* pHa  = devptr<__half>(d_Ha);
    __half* pHb  = devptr<__half>(d_Hb);
    __half* pHc  = devptr<__half>(d_Hc);
    __half* pxph = devptr<__half>(d_xph);
    __half* pCh0 = devptr<__half>(d_Ch0);
    __half* pCh1 = devptr<__half>(d_Ch1);
    int*    pdeg  = devptr<int>(d_deg);
    int*    prs   = devptr<int>(d_rs);
    int*    pbs   = devptr<int>(d_bsums);
    int*    pes   = devptr<int>(d_esrc);
    float4* pbf   = devptr<float4>(d_basF);
    int*    pdegc = devptr<int>(d_degc);
    int*    prsc  = devptr<int>(d_rsc);
    int*    pcurc = devptr<int>(d_curc);
    int*    pesC  = devptr<int>(d_esrcC);
    float4* pbfC  = devptr<float4>(d_basFC);
    int*    ptick = devptr<int>(d_tickS);

    // prolog: 3 launches before first conv (ncu -s 5 lands on fuse_l0)
    k_prep<<<Ee/256,256>>>(dst, pos, batch, x);
    k_scan12<<<256,1024>>>(pdeg, prs, Nn, ptick);
    k_scatter<<<Ee/256,256>>>(src, dst, ea);

    // fine layers, fused BN stats; grid = Nn/32 (D=4, 8 warps)
    k_fuse2<16, 8,false><<<Nn/32,256>>>(pH0, nullptr, (const float*)d_in[5],  pHa, prs, pbs, pes, pbf, 0, 10, -1, -1, (const float*)d_in[6],  (const float*)d_in[7]);
    k_fuse2< 8,16,false><<<Nn/32,256>>>(pHa, nullptr, (const float*)d_in[8],  pHb, prs, pbs, pes, pbf, 1,  8,  0, -1, (const float*)d_in[9],  (const float*)d_in[10]);
    k_fuse2<16,16,false><<<Nn/32,256>>>(pHb, nullptr, (const float*)d_in[11], pHc, prs, pbs, pes, pbf, 2, 16,  1, -1, (const float*)d_in[12], (const float*)d_in[13]);
    k_fuse2<16,16,false><<<Nn/32,256>>>(pHc, nullptr, (const float*)d_in[14], pHa, prs, pbs, pes, pbf, 3, 16,  2, -1, (const float*)d_in[15], (const float*)d_in[16]);
    k_fuse2<16,16,false><<<Nn/32,256>>>(pHa, nullptr, (const float*)d_in[17], pHb, prs, pbs, pes, pbf, 4, 16,  3, -1, (const float*)d_in[18], (const float*)d_in[19]);
    k_fuse2<16,32,true ><<<Nn/32,256>>>(pHb, pHc,     (const float*)d_in[20], pHa, prs, pbs, pes, pbf, 5, 16,  4,  2, (const float*)d_in[21], (const float*)d_in[22]);

    // pooling + coarse graph build
    k_poolmax<<<(Nn*32)/256,256>>>(pHa);
    k_cellfin<<<(Sn*32+255)/256,256>>>();
    k_cedges<<<Ee/256,256>>>(src, dst);
    k_scan12<<<8,1024>>>(pdegc, prsc, Sn, ptick+1);
    k_scan3<<<(Sn+255)/256,256>>>(pdegc, prsc, pcurc, Sn);
    k_scatterC<<<Ee/256,256>>>();

    // coarse layers (weighted BN, fused stats)
    k_fuseC<<<Sn,256>>>(pxph, (const float*)d_in[23], pCh0, prsc, pesC, pbfC, 6, -1, (const float*)d_in[24], (const float*)d_in[25]);
    k_fuseC<<<Sn,256>>>(pCh0, (const float*)d_in[26], pCh1, prsc, pesC, pbfC, 7,  6, (const float*)d_in[27], (const float*)d_in[28]);

    k_final<<<Bn,256>>>(pCh1, fcW, out);

    // epilogue: restore zeroed scratch for the next replay
    k_epi<<<512,256>>>();
    (void)in_sizes; (void)n_in; (void)out_size;
}

// round 14
// speedup vs baseline: 1.5453x; 1.0387x over previous
#include <cuda_runtime.h>
#include <cuda_fp16.h>
#include <math.h>

#define Nn   262144
#define Ee   2097152
#define Bn   16
#define GXn  22
#define Gn   484
#define Sn   7744
#define EPSn 1e-5f
#define SXn  (16.0f/346.0f)
#define SYn  (12.0f/260.0f)
#define NCPY 64
#define MARKW ((Bn*Gn*Gn + 31)/32)

// ---------------- scratch (statically zero-initialized; k_epi restores) -------
__device__ int      d_deg [Nn];        // self-restoring (hist + atomicSub)
__device__ int      d_rs  [Nn+1];
__device__ float4   d_basF[Ee];        // (srcbits, b0, b1, b2)
__device__ float4   d_S4  [Nn];        // per-dst basis sums (s0,s1,s2) from layer 0
__device__ float4   d_S4C [Sn];        // coarse basis sums from layer 6
__device__ int      d_bsums[1024];
__device__ int      d_cid [Nn];
__device__ int      d_ccnt[Sn];        // epi-zeroed
__device__ float    d_pp  [Sn*2];      // epi-zeroed
__device__ unsigned d_xpe [Sn*32];     // epi-zeroed
__device__ __half   d_xph [Sn*32];
__device__ float    d_wv  [Sn];
__device__ unsigned d_markb[MARKW];    // epi-zeroed
__device__ int      d_EcD [1];         // epi-zeroed
__device__ int      d_csrc[Ee];
__device__ int      d_cdst[Ee];
__device__ int      d_degc[Sn];        // epi-zeroed
__device__ int      d_rsc [Sn+1];
__device__ int      d_curc[Sn+1];
__device__ float4   d_basFC[Ee];
__device__ unsigned d_mxD [1];         // epi-zeroed
__device__ float    d_twD [1];         // epi-zeroed
__device__ __half   d_H0 [(size_t)Nn*16];
__device__ __half   d_Ha [(size_t)Nn*32];
__device__ __half   d_Hb [(size_t)Nn*32];
__device__ __half   d_Hc [(size_t)Nn*32];
__device__ __half   d_Ch0[Sn*32];
__device__ __half   d_Ch1[Sn*32];
__device__ float    d_bnaccM[8][NCPY][128];   // epi-zeroed
__device__ float    d_ssbL[8][64];
__device__ int      d_tickS[2];        // epi-zeroed
__device__ int      d_tickL[8];        // epi-zeroed

// ---------------- helpers ----------------
__device__ __forceinline__ unsigned encf(float f){
    unsigned u = __float_as_uint(f);
    return (u & 0x80000000u) ? ~u : (u | 0x80000000u);
}
__device__ __forceinline__ float decf(unsigned u){
    return (u & 0x80000000u) ? __uint_as_float(u & 0x7FFFFFFFu) : __uint_as_float(~u);
}

// ---------------- prep: hist + cells + half-packed input ----------------
__global__ void k_prep(const int* __restrict__ dst, const float* __restrict__ pos,
                       const int* __restrict__ batch, const float* __restrict__ x){
    int e = blockIdx.x*blockDim.x + threadIdx.x;
    if (e < Ee) atomicAdd(&d_deg[dst[e]], 1);
    if (e < Nn){
        float px = pos[2*(size_t)e], py = pos[2*(size_t)e+1];
        int cx = min(max((int)floorf(px / SXn), 0), GXn-1);
        int cy = min(max((int)floorf(py / SYn), 0), GXn-1);
        int cid = batch[e]*Gn + cy*GXn + cx;
        d_cid[e] = cid;
        atomicAdd(&d_ccnt[cid], 1);
        atomicAdd(&d_pp[2*cid],   px);
        atomicAdd(&d_pp[2*cid+1], py);
        const float* xr = x + (size_t)e*10;
        __half* hr = d_H0 + (size_t)e*16;
        #pragma unroll
        for (int i=0;i<10;i++) hr[i] = __float2half(xr[i]);
        #pragma unroll
        for (int i=10;i<16;i++) hr[i] = __float2half(0.f);
    }
}

// ---------------- scan12 ----------------
__global__ void k_scan12(const int* __restrict__ in, int* __restrict__ out, int n,
                         int* __restrict__ tick){
    __shared__ int sh[1025];
    __shared__ int isLast;
    int t = threadIdx.x;
    int base = blockIdx.x*1024;
    int v = (base+t < n) ? in[base+t] : 0;
    sh[t] = v; __syncthreads();
    for (int off=1; off<1024; off<<=1){
        int a = (t>=off) ? sh[t-off] : 0;
        __syncthreads();
        sh[t] += a;
        __syncthreads();
    }
    if (base+t < n) out[base+t] = sh[t]-v;
    if (t==1023) d_bsums[blockIdx.x] = sh[1023];
    __threadfence();
    if (t==0) isLast = (atomicAdd(tick,1) == (int)gridDim.x-1);
    __syncthreads();
    if (!isLast) return;
    int nb = gridDim.x;
    int bv = (t<nb) ? __ldcg(&d_bsums[t]) : 0;
    __syncthreads();
    sh[t] = bv; __syncthreads();
    for (int off=1; off<1024; off<<=1){
        int a = (t>=off) ? sh[t-off] : 0;
        __syncthreads();
        sh[t] += a;
        __syncthreads();
    }
    if (t<=nb) d_bsums[t] = sh[t]-((t<nb)?bv:0);
}
__global__ void k_scan3(const int* __restrict__ in, int* __restrict__ out,
                        int* __restrict__ cur, int n){
    int i = blockIdx.x*blockDim.x + threadIdx.x;
    if (i >= n) return;
    int v = out[i] + d_bsums[i>>10];
    out[i] = v; cur[i] = v;
    if (i == n-1){ int tot = v + in[i]; out[n]=tot; cur[n]=tot; }
}

// scatter: (srcbits, b0, b1, b2) — b3 = 1-b0-b1-b2 implicit
__global__ void k_scatter(const int* __restrict__ src, const int* __restrict__ dst,
                          const float* __restrict__ ea){
    int e = blockIdx.x*blockDim.x + threadIdx.x;
    if (e >= Ee) return;
    float2 f = reinterpret_cast<const float2*>(ea)[e];
    float f0 = fminf(fmaxf(f.x, 0.f), 1.f);
    float f1 = fminf(fmaxf(f.y, 0.f), 1.f);
    int d = dst[e];
    int old = atomicSub(&d_deg[d], 1);
    int p = d_rs[d] + d_bsums[d>>10] + (old - 1);
    d_basF[p] = make_float4(__int_as_float(src[e]),
                            (1.f-f0)*(1.f-f1), f0*(1.f-f1), (1.f-f0)*f1);
}

// ---------- BN stats tail ----------
__device__ __forceinline__ void bn_stats_tail(const float* g, const float* b,
                                              int layer, int cout, float denom, int useTw){
    __shared__ float part[2][128];
    __shared__ float tot[128];
    int t = threadIdx.x;
    int idx = t & 127, grp = t >> 7;
    float S = 0.f;
    for (int k = grp; k < NCPY; k += 2) S += __ldcg(&d_bnaccM[layer][k][idx]);
    part[grp][idx] = S;
    __syncthreads();
    if (t < 128) tot[t] = part[0][t] + part[1][t];
    __syncthreads();
    if (t < cout){
        float dn = useTw ? __ldcg(&d_twD[0]) : denom;
        float m = tot[t]/dn;
        float v = tot[64+t]/dn - m*m;
        float a = g[t]*rsqrtf(v + EPSn);
        d_ssbL[layer][t]    = a;
        d_ssbL[layer][32+t] = b[t] - m*a;
    }
}

// ---------------- fused fine layer ----------------
// moments: M = Σx, A0..A2 = Σ b_k x ; A3 = M-A0-A1-A2 ; s3 = deg-s0-s1-s2
template<int CINH, int COUT, bool RESID, bool SUMS>
__global__ void k_fuse2(const __half* __restrict__ X1, const __half* __restrict__ X2,
                        const float* __restrict__ W, __half* __restrict__ uout,
                        const int* __restrict__ rs, const int* __restrict__ bs,
                        const float4* __restrict__ basF,
                        int layer, int wcin, int ab1, int ab2,
                        const float* __restrict__ g, const float* __restrict__ bb_){
    constexpr int CPL  = CINH/8;
    constexpr int NOUT = COUT/8;
    __shared__ float Wsh[4*CINH*COUT];
    __shared__ float A1s[32], B1s[32], A2s[32];
    __shared__ float As[8][4][4][CINH];
    __shared__ float sv[8][32][NOUT];
    __shared__ int   isLast;
    int tid = threadIdx.x;
    for (int idx = tid; idx < 4*wcin*COUT; idx += 256) Wsh[idx] = W[idx];
    if (tid < 32){
        A1s[tid] = (ab1 >= 0) ? d_ssbL[ab1][tid]    : 1.f;
        float b1 = (ab1 >= 0) ? d_ssbL[ab1][32+tid] : 0.f;
        A2s[tid] = (ab2 >= 0) ? d_ssbL[ab2][tid]    : 0.f;
        float b2 = (ab2 >= 0) ? d_ssbL[ab2][32+tid] : 0.f;
        B1s[tid] = b1 + b2;
    }
    __syncthreads();
    int w = tid >> 5, lane = tid & 31;
    int sub = lane >> 3, il = lane & 7;
    int d = (blockIdx.x*8 + w)*4 + sub;
    int beg = rs[d]   + bs[d>>10];
    int end = rs[d+1] + bs[(d+1)>>10];

    float a0[CPL], a1[CPL], a2[CPL], am[CPL];
    float e0[CPL], e1[CPL], e2[CPL], em[CPL];
    float k0=0.f, k1=0.f, k2=0.f;
    #pragma unroll
    for (int cc=0;cc<CPL;cc++){
        a0[cc]=a1[cc]=a2[cc]=am[cc]=0.f;
        e0[cc]=e1[cc]=e2[cc]=em[cc]=0.f;
    }
    const __half2* X1h = reinterpret_cast<const __half2*>(X1);
    const __half2* X2h = reinterpret_cast<const __half2*>(X2);

    #pragma unroll 2
    for (int p = beg; p < end; p++){
        float4 q = __ldg(&basF[p]);
        int sa = __float_as_int(q.x);
        if (SUMS){ k0 += q.y; k1 += q.z; k2 += q.w; }
        if (CPL == 2){
            float2 xa = __half22float2(X1h[(size_t)sa*8 + il]);
            am[0] += xa.x;       am[CPL-1] += xa.y;
            a0[0] += q.y*xa.x;   a0[CPL-1] += q.y*xa.y;
            a1[0] += q.z*xa.x;   a1[CPL-1] += q.z*xa.y;
            a2[0] += q.w*xa.x;   a2[CPL-1] += q.w*xa.y;
            if (RESID){
                float2 ya = __half22float2(X2h[(size_t)sa*8 + il]);
                em[0] += ya.x;       em[CPL-1] += ya.y;
                e0[0] += q.y*ya.x;   e0[CPL-1] += q.y*ya.y;
                e1[0] += q.z*ya.x;   e1[CPL-1] += q.z*ya.y;
                e2[0] += q.w*ya.x;   e2[CPL-1] += q.w*ya.y;
            }
        } else {
            float xa = __half2float(X1[(size_t)sa*8 + il]);
            am[0] += xa;
            a0[0] += q.y*xa; a1[0] += q.z*xa; a2[0] += q.w*xa;
        }
    }

    // per-dst basis sums: compute (layer 0) or load (layers 1..5)
    float s0, s1, s2;
    if (SUMS){
        s0 = k0; s1 = k1; s2 = k2;
        if (il == 0) d_S4[d] = make_float4(s0, s1, s2, 0.f);
    } else {
        float4 S = __ldg(&d_S4[d]);
        s0 = S.x; s1 = S.y; s2 = S.z;
    }
    float fdeg = (float)(end - beg);
    float s3 = fdeg - s0 - s1 - s2;

    #pragma unroll
    for (int cc=0;cc<CPL;cc++){
        int ch = il*CPL + cc;
        float av1 = A1s[ch], av2 = A2s[ch], bbv = B1s[ch];
        float a3 = am[cc] - a0[cc] - a1[cc] - a2[cc];
        float r0 = av1*a0[cc] + bbv*s0;
        float r1 = av1*a1[cc] + bbv*s1;
        float r2 = av1*a2[cc] + bbv*s2;
        float r3 = av1*a3     + bbv*s3;
        if (RESID){
            float ee3 = em[cc] - e0[cc] - e1[cc] - e2[cc];
            r0 += av2*e0[cc]; r1 += av2*e1[cc]; r2 += av2*e2[cc]; r3 += av2*ee3;
        }
        As[w][sub][0][ch] = r0;
        As[w][sub][1][ch] = r1;
        As[w][sub][2][ch] = r2;
        As[w][sub][3][ch] = r3;
    }
    __syncwarp();
    int dg = end - beg; if (dg < 1) dg = 1;
    float inv = 1.f / (float)dg;
    #pragma unroll
    for (int q=0;q<NOUT;q++){
        int ch = (lane & 7) + 8*q;
        float v = 0.f;
        for (int k=0;k<4;k++){
            const float* ak = &As[w][sub][k][0];
            const float* wk = &Wsh[k*wcin*COUT + ch];
            for (int i=0;i<wcin;i++) v += ak[i] * wk[i*COUT];
        }
        v *= inv;
        v = (v > 0.f) ? v : expm1f(v);
        uout[(size_t)d*COUT + ch] = __float2half(v);
        sv[w][lane][q] = v;
    }
    __syncthreads();
    if (w == 0 && lane < COUT){
        float S = 0.f, Q = 0.f;
        int cl = lane & 7, q = lane >> 3;
        #pragma unroll
        for (int j=0;j<8;j++){
            #pragma unroll
            for (int s2i=0;s2i<4;s2i++){
                float v = sv[j][s2i*8 + cl][q];
                S += v; Q += v*v;
            }
        }
        int cp = blockIdx.x & (NCPY-1);
        atomicAdd(&d_bnaccM[layer][cp][lane],    S);
        atomicAdd(&d_bnaccM[layer][cp][64+lane], Q);
    }
    __threadfence();
    __syncthreads();
    if (tid == 0) isLast = (atomicAdd(&d_tickL[layer],1) == (int)gridDim.x-1);
    __syncthreads();
    if (isLast) bn_stats_tail(g, bb_, layer, COUT, (float)Nn, 0);
}

// ---------------- fused coarse layer: block per dst ----------------
__global__ void k_fuseC(const __half* __restrict__ X1, const float* __restrict__ W,
                        __half* __restrict__ uout, const int* __restrict__ rs,
                        const float4* __restrict__ basF, int layer, int ab1, int sums,
                        const float* __restrict__ g, const float* __restrict__ bb_){
    __shared__ float Wsh[4*32*32];
    __shared__ float A1s[32], B1s[32];
    __shared__ float accS[8][4][32];   // slots 0..2 = A0..A2, 3 = M
    __shared__ float sKS[8][4];
    __shared__ float Afin[4][32];
    __shared__ float sks[4];
    __shared__ int   isLast;
    int d = blockIdx.x, tid = threadIdx.x;
    int w = tid >> 5, lane = tid & 31;
    for (int idx = tid; idx < 4096; idx += 256) Wsh[idx] = W[idx];
    if (tid < 32){
        A1s[tid] = (ab1 >= 0) ? d_ssbL[ab1][tid]    : 1.f;
        B1s[tid] = (ab1 >= 0) ? d_ssbL[ab1][32+tid] : 0.f;
    }
    __syncthreads();
    int beg = rs[d], end = rs[d+1];
    float a0=0,a1=0,a2=0,am=0, k0=0,k1=0,k2=0;
    #pragma unroll 2
    for (int p = beg + w; p < end; p += 8){
        float4 q = __ldg(&basF[p]);
        int s = __float_as_int(q.x);
        float xv = __half2float(X1[(size_t)s*32 + lane]);
        am += xv;
        a0 += q.y*xv; a1 += q.z*xv; a2 += q.w*xv;
        if (sums){ k0 += q.y; k1 += q.z; k2 += q.w; }
    }
    accS[w][0][lane]=a0; accS[w][1][lane]=a1; accS[w][2][lane]=a2; accS[w][3][lane]=am;
    if (lane == 0){ sKS[w][0]=k0; sKS[w][1]=k1; sKS[w][2]=k2; }
    __syncthreads();
    if (tid < 128){
        int k = tid >> 5, i = tid & 31;
        float r = 0.f;
        #pragma unroll
        for (int j = 0; j < 8; j++) r += accS[j][k][i];
        Afin[k][i] = r;
    }
    if (tid >= 128 && tid < 131 && sums){
        int k = tid - 128;
        float r = 0.f;
        #pragma unroll
        for (int j = 0; j < 8; j++) r += sKS[j][k];
        sks[k] = r;
    }
    __syncthreads();
    if (w == 0){
        float s0, s1, s2;
        if (sums){
            s0 = sks[0]; s1 = sks[1]; s2 = sks[2];
            if (lane == 0) d_S4C[d] = make_float4(s0, s1, s2, 0.f);
        } else {
            float4 S = __ldg(&d_S4C[d]);
            s0 = S.x; s1 = S.y; s2 = S.z;
        }
        float fdeg = (float)(end - beg);
        float s3 = fdeg - s0 - s1 - s2;
        int i = lane;
        float r0 = Afin[0][i], r1 = Afin[1][i], r2 = Afin[2][i];
        float r3 = Afin[3][i] - r0 - r1 - r2;
        Afin[0][i] = A1s[i]*r0 + B1s[i]*s0;
        Afin[1][i] = A1s[i]*r1 + B1s[i]*s1;
        Afin[2][i] = A1s[i]*r2 + B1s[i]*s2;
        Afin[3][i] = A1s[i]*r3 + B1s[i]*s3;
        __syncwarp();
        float v = 0.f;
        #pragma unroll
        for (int k = 0; k < 4; k++)
            for (int i2 = 0; i2 < 32; i2++)
                v += Afin[k][i2] * Wsh[(k*32+i2)*32 + lane];
        int dg = end - beg; if (dg < 1) dg = 1;
        v /= (float)dg;
        v = (v > 0.f) ? v : expm1f(v);
        uout[(size_t)d*32 + lane] = __float2half(v);
        float ww = d_wv[d];
        int cp = blockIdx.x & (NCPY-1);
        atomicAdd(&d_bnaccM[layer][cp][lane],    ww*v);
        atomicAdd(&d_bnaccM[layer][cp][64+lane], ww*v*v);
    }
    __threadfence();
    __syncthreads();
    if (tid == 0) isLast = (atomicAdd(&d_tickL[layer],1) == (int)gridDim.x-1);
    __syncthreads();
    if (isLast) bn_stats_tail(g, bb_, layer, 32, 0.f, 1);
}

// ---------------- pooling ----------------
__global__ void k_poolmax(const __half* __restrict__ u){
    int idx = blockIdx.x*blockDim.x + threadIdx.x;
    if (idx >= Nn*32) return;
    int n = idx >> 5, c = idx & 31;
    float v = __half2float(u[idx])*d_ssbL[5][c] + d_ssbL[5][32+c];
    atomicMax(&d_xpe[d_cid[n]*32 + c], encf(v));
}

__global__ void k_cellfin(){
    int idx = blockIdx.x*blockDim.x + threadIdx.x;
    if (idx >= Sn*32) return;
    int s = idx >> 5, c = idx & 31;
    int cnt = d_ccnt[s];
    if (c == 0){
        float inv = 1.f / (float)(cnt > 1 ? cnt : 1);
        d_pp[2*s]   *= inv;
        d_pp[2*s+1] *= inv;
        float w = (cnt > 0) ? 1.f : 0.f;
        d_wv[s] = w;
        if (cnt > 0) atomicAdd(&d_twD[0], 1.f);
    }
    d_xph[idx] = __float2half((cnt > 0) ? decf(d_xpe[idx]) : 0.f);
}

__global__ void k_cedges(const int* __restrict__ src, const int* __restrict__ dst){
    int e = blockIdx.x*blockDim.x + threadIdx.x;
    int cs = d_cid[src[e]], cd = d_cid[dst[e]];
    bool win = false;
    float m = 0.f;
    if (cs != cd){
        int b = cs / Gn;
        int key = b*Gn*Gn + (cs - b*Gn)*Gn + (cd - b*Gn);
        unsigned bit = 1u << (key & 31);
        unsigned old = atomicOr(&d_markb[key >> 5], bit);
        if (!(old & bit)){
            win = true;
            float cx = d_pp[2*cs]   - d_pp[2*cd];
            float cy = d_pp[2*cs+1] - d_pp[2*cd+1];
            m = fmaxf(fabsf(cx), fabsf(cy));
        }
    }
    unsigned wmask = __ballot_sync(0xFFFFFFFFu, win);
    float wm = m;
    #pragma unroll
    for (int o = 16; o; o >>= 1) wm = fmaxf(wm, __shfl_xor_sync(0xFFFFFFFFu, wm, o));
    int lane = threadIdx.x & 31;
    int nwin = __popc(wmask);
    int base = 0;
    if (lane == 0 && nwin){
        base = atomicAdd(&d_EcD[0], nwin);
        atomicMax(&d_mxD[0], __float_as_uint(wm));
    }
    base = __shfl_sync(0xFFFFFFFFu, base, 0);
    if (win){
        int i = base + __popc(wmask & ((1u << lane) - 1));
        d_csrc[i] = cs; d_cdst[i] = cd;
        atomicAdd(&d_degc[cd], 1);
    }
}

__global__ void k_scatterC(){
    int i = blockIdx.x*blockDim.x + threadIdx.x;
    if (i >= d_EcD[0]) return;
    int cs = d_csrc[i], cd = d_cdst[i];
    int p = atomicAdd(&d_curc[cd], 1);
    float mx = __uint_as_float(d_mxD[0]);
    float den = 2.f*mx + 1e-12f;
    float f0 = (d_pp[2*cs]   - d_pp[2*cd])   / den + 0.5f;
    float f1 = (d_pp[2*cs+1] - d_pp[2*cd+1]) / den + 0.5f;
    f0 = fminf(fmaxf(f0, 0.f), 1.f);
    f1 = fminf(fmaxf(f1, 0.f), 1.f);
    d_basFC[p] = make_float4(__int_as_float(cs),
                             (1.f-f0)*(1.f-f1), f0*(1.f-f1), (1.f-f0)*f1);
}

// ---------------- final ----------------
__global__ void k_final(const __half* __restrict__ h, const float* __restrict__ fcW,
                        float* __restrict__ out){
    __shared__ float ss[8][33];
    __shared__ float sw8[8];
    __shared__ float gm[32];
    __shared__ float swv;
    int b = blockIdx.x;
    int lane = threadIdx.x & 31, w = threadIdx.x >> 5;
    float a7 = d_ssbL[7][lane], b7 = d_ssbL[7][32+lane];
    float acc = 0.f, accw = 0.f;
    for (int s = b*Gn + w; s < (b+1)*Gn; s += 8){
        float ww = d_wv[s];
        acc  += ww * (a7*__half2float(h[(size_t)s*32 + lane]) + b7);
        accw += ww;
    }
    ss[w][lane] = acc;
    if (lane == 0) sw8[w] = accw;
    __syncthreads();
    if (threadIdx.x < 32){
        float S = 0.f;
        #pragma unroll
        for (int j=0;j<8;j++) S += ss[j][threadIdx.x];
        gm[threadIdx.x] = S;
    }
    if (threadIdx.x == 0){
        float W = 0.f;
        #pragma unroll
        for (int j=0;j<8;j++) W += sw8[j];
        swv = W;
    }
    __syncthreads();
    if (threadIdx.x < 10){
        float o = 0.f;
        #pragma unroll
        for (int c=0;c<32;c++) o += (gm[c]/swv) * fcW[c*10 + threadIdx.x];
        out[b*10 + threadIdx.x] = o;
    }
}

// ---------------- epilogue: restore scratch for next graph replay -------------
__global__ void k_epi(){
    int i = blockIdx.x*blockDim.x + threadIdx.x;
    int st = gridDim.x*blockDim.x;
    for (int j=i; j<MARKW; j+=st) d_markb[j]=0u;
    for (int j=i; j<Sn;    j+=st){ d_ccnt[j]=0; d_degc[j]=0; }
    for (int j=i; j<Sn*2;  j+=st) d_pp[j]=0.f;
    for (int j=i; j<Sn*32; j+=st) d_xpe[j]=0u;
    float* bm = &d_bnaccM[0][0][0];
    for (int j=i; j<8*NCPY*128; j+=st) bm[j]=0.f;
    if (i < 2) d_tickS[i]=0;
    if (i < 8) d_tickL[i]=0;
    if (i==0){ d_EcD[0]=0; d_mxD[0]=0u; d_twD[0]=0.f; }
}

// ---------------- host ----------------
template <typename T>
static T* devptr(const void* sym){
    void* p = nullptr;
    cudaGetSymbolAddress(&p, sym);
    return (T*)p;
}

extern "C" void kernel_launch(void* const* d_in, const int* in_sizes, int n_in,
                              void* d_out, int out_size){
    const float* x     = (const float*)d_in[0];
    const float* pos   = (const float*)d_in[1];
    const int*   batch = (const int*)  d_in[2];
    const int*   ei    = (const int*)  d_in[3];
    const int*   src   = ei;
    const int*   dst   = ei + Ee;
    const float* ea    = (const float*)d_in[4];
    const float* fcW   = (const float*)d_in[29];
    float* out = (float*)d_out;

    __half* pH0  = devptr<__half>(d_H0);
    __half* pHa  = devptr<__half>(d_Ha);
    __half* pHb  = devptr<__half>(d_Hb);
    __half* pHc  = devptr<__half>(d_Hc);
    __half* pxph = devptr<__half>(d_xph);
    __half* pCh0 = devptr<__half>(d_Ch0);
    __half* pCh1 = devptr<__half>(d_Ch1);
    int*    pdeg  = devptr<int>(d_deg);
    int*    prs   = devptr<int>(d_rs);
    int*    pbs   = devptr<int>(d_bsums);
    float4* pbf   = devptr<float4>(d_basF);
    int*    pdegc = devptr<int>(d_degc);
    int*    prsc  = devptr<int>(d_rsc);
    int*    pcurc = devptr<int>(d_curc);
    float4* pbfC  = devptr<float4>(d_basFC);
    int*    ptick = devptr<int>(d_tickS);

    // prolog: 3 launches before first conv (ncu -s 5 lands on fuse_l0)
    k_prep<<<Ee/256,256>>>(dst, pos, batch, x);
    k_scan12<<<256,1024>>>(pdeg, prs, Nn, ptick);
    k_scatter<<<Ee/256,256>>>(src, dst, ea);

    // fine layers; layer 0 computes per-dst basis sums, others reuse
    k_fuse2<16, 8,false,true ><<<Nn/32,256>>>(pH0, nullptr, (const float*)d_in[5],  pHa, prs, pbs, pbf, 0, 10, -1, -1, (const float*)d_in[6],  (const float*)d_in[7]);
    k_fuse2< 8,16,false,false><<<Nn/32,256>>>(pHa, nullptr, (const float*)d_in[8],  pHb, prs, pbs, pbf, 1,  8,  0, -1, (const float*)d_in[9],  (const float*)d_in[10]);
    k_fuse2<16,16,false,false><<<Nn/32,256>>>(pHb, nullptr, (const float*)d_in[11], pHc, prs, pbs, pbf, 2, 16,  1, -1, (const float*)d_in[12], (const float*)d_in[13]);
    k_fuse2<16,16,false,false><<<Nn/32,256>>>(pHc, nullptr, (const float*)d_in[14], pHa, prs, pbs, pbf, 3, 16,  2, -1, (const float*)d_in[15], (const float*)d_in[16]);
    k_fuse2<16,16,false,false><<<Nn/32,256>>>(pHa, nullptr, (const float*)d_in[17], pHb, prs, pbs, pbf, 4, 16,  3, -1, (const float*)d_in[18], (const float*)d_in[19]);
    k_fuse2<16,32,true ,false><<<Nn/32,256>>>(pHb, pHc,     (const float*)d_in[20], pHa, prs, pbs, pbf, 5, 16,  4,  2, (const float*)d_in[21], (const float*)d_in[22]);

    // pooling + coarse graph build
    k_poolmax<<<(Nn*32)/256,256>>>(pHa);
    k_cellfin<<<(Sn*32+255)/256,256>>>();
    k_cedges<<<Ee/256,256>>>(src, dst);
    k_scan12<<<8,1024>>>(pdegc, prsc, Sn, ptick+1);
    k_scan3<<<(Sn+255)/256,256>>>(pdegc, prsc, pcurc, Sn);
    k_scatterC<<<Ee/256,256>>>();

    // coarse layers; layer 6 computes coarse basis sums, layer 7 reuses
    k_fuseC<<<Sn,256>>>(pxph, (const float*)d_in[23], pCh0, prsc, pbfC, 6, -1, 1, (const float*)d_in[24], (const float*)d_in[25]);
    k_fuseC<<<Sn,256>>>(pCh0, (const float*)d_in[26], pCh1, prsc, pbfC, 7,  6, 0, (const float*)d_in[27], (const float*)d_in[28]);

    k_final<<<Bn,256>>>(pCh1, fcW, out);

    // epilogue: restore zeroed scratch for the next replay
    k_epi<<<512,256>>>();
    (void)in_sizes; (void)n_in; (void)out_size;
}

// round 17
// speedup vs baseline: 1.5604x; 1.0098x over previous
#include <cuda_runtime.h>
#include <cuda_fp16.h>
#include <math.h>

#define Nn   262144
#define Ee   2097152
#define Bn   16
#define GXn  22
#define Gn   484
#define Sn   7744
#define EPSn 1e-5f
#define SXn  (16.0f/346.0f)
#define SYn  (12.0f/260.0f)
#define NCPY 64
#define MARKW ((Bn*Gn*Gn + 31)/32)

// ---------------- scratch (statically zero-initialized; k_epi restores) -------
__device__ int      d_deg [Nn];        // self-restoring (hist + atomicSub)
__device__ int      d_rs  [Nn+1];
__device__ float4   d_basF[Ee];        // (srcbits, b0, b1, b2)
__device__ float4   d_S4  [Nn];        // per-dst basis sums from layer 0
__device__ float4   d_S4C [Sn];        // coarse basis sums from layer 6
__device__ int      d_bsums [1024];    // fine scan block sums (LIVE through fine layers)
__device__ int      d_bsumsC[16];      // coarse scan block sums (separate! no aliasing)
__device__ int      d_cid [Nn];
__device__ int      d_ccnt[Sn];        // epi-zeroed
__device__ float    d_pp  [Sn*2];      // epi-zeroed
__device__ unsigned d_xpe [Sn*32];     // epi-zeroed
__device__ __half   d_xph [Sn*32];
__device__ float    d_wv  [Sn];
__device__ unsigned d_markb[MARKW];    // epi-zeroed
__device__ int      d_EcD [1];         // epi-zeroed
__device__ int      d_csrc[Ee];
__device__ int      d_cdst[Ee];
__device__ int      d_degc[Sn];        // epi-zeroed
__device__ int      d_rsc [Sn+1];
__device__ int      d_curc[Sn+1];
__device__ float4   d_basFC[Ee];
__device__ unsigned d_mxD [1];         // epi-zeroed
__device__ float    d_twD [1];         // epi-zeroed
__device__ __half   d_H0 [(size_t)Nn*16];
__device__ __half   d_Ha [(size_t)Nn*32];
__device__ __half   d_Hb [(size_t)Nn*32];
__device__ __half   d_Hc [(size_t)Nn*32];
__device__ __half   d_Ch0[Sn*32];
__device__ __half   d_Ch1[Sn*32];
__device__ float    d_bnaccM[8][NCPY][128];   // epi-zeroed
__device__ float    d_ssbL[8][64];
__device__ int      d_tickS[2];        // epi-zeroed
__device__ int      d_tickL[8];        // epi-zeroed

// ---------------- helpers ----------------
__device__ __forceinline__ unsigned encf(float f){
    unsigned u = __float_as_uint(f);
    return (u & 0x80000000u) ? ~u : (u | 0x80000000u);
}
__device__ __forceinline__ float decf(unsigned u){
    return (u & 0x80000000u) ? __uint_as_float(u & 0x7FFFFFFFu) : __uint_as_float(~u);
}

// ---------------- prep: hist + cells + half-packed input ----------------
__global__ void k_prep(const int* __restrict__ dst, const float* __restrict__ pos,
                       const int* __restrict__ batch, const float* __restrict__ x){
    int e = blockIdx.x*blockDim.x + threadIdx.x;
    if (e < Ee) atomicAdd(&d_deg[dst[e]], 1);
    if (e < Nn){
        float px = pos[2*(size_t)e], py = pos[2*(size_t)e+1];
        int cx = min(max((int)floorf(px / SXn), 0), GXn-1);
        int cy = min(max((int)floorf(py / SYn), 0), GXn-1);
        int cid = batch[e]*Gn + cy*GXn + cx;
        d_cid[e] = cid;
        atomicAdd(&d_ccnt[cid], 1);
        atomicAdd(&d_pp[2*cid],   px);
        atomicAdd(&d_pp[2*cid+1], py);
        const float* xr = x + (size_t)e*10;
        __half* hr = d_H0 + (size_t)e*16;
        #pragma unroll
        for (int i=0;i<10;i++) hr[i] = __float2half(xr[i]);
        #pragma unroll
        for (int i=10;i<16;i++) hr[i] = __float2half(0.f);
    }
}

// cell means + wv + tw (pp normalized BEFORE scatter computes mx)
__global__ void k_cellpp(){
    int s = blockIdx.x*blockDim.x + threadIdx.x;
    if (s >= Sn) return;
    int cnt = d_ccnt[s];
    float inv = 1.f / (float)(cnt > 1 ? cnt : 1);
    d_pp[2*s]   *= inv;
    d_pp[2*s+1] *= inv;
    float w = (cnt > 0) ? 1.f : 0.f;
    d_wv[s] = w;
    if (cnt > 0) atomicAdd(&d_twD[0], 1.f);
}

// ---------------- scan12 (parameterized block-sums array) ----------------
__global__ void k_scan12(const int* __restrict__ in, int* __restrict__ out, int n,
                         int* __restrict__ tick, int* __restrict__ bsums){
    __shared__ int sh[1025];
    __shared__ int isLast;
    int t = threadIdx.x;
    int base = blockIdx.x*1024;
    int v = (base+t < n) ? in[base+t] : 0;
    sh[t] = v; __syncthreads();
    for (int off=1; off<1024; off<<=1){
        int a = (t>=off) ? sh[t-off] : 0;
        __syncthreads();
        sh[t] += a;
        __syncthreads();
    }
    if (base+t < n) out[base+t] = sh[t]-v;
    if (t==1023) bsums[blockIdx.x] = sh[1023];
    __threadfence();
    if (t==0) isLast = (atomicAdd(tick,1) == (int)gridDim.x-1);
    __syncthreads();
    if (!isLast) return;
    int nb = gridDim.x;
    int bv = (t<nb) ? __ldcg(&bsums[t]) : 0;
    __syncthreads();
    sh[t] = bv; __syncthreads();
    for (int off=1; off<1024; off<<=1){
        int a = (t>=off) ? sh[t-off] : 0;
        __syncthreads();
        sh[t] += a;
        __syncthreads();
    }
    if (t<=nb) bsums[t] = sh[t]-((t<nb)?bv:0);
}
__global__ void k_scan3(const int* __restrict__ in, int* __restrict__ out,
                        int* __restrict__ cur, int n, const int* __restrict__ bsums){
    int i = blockIdx.x*blockDim.x + threadIdx.x;
    if (i >= n) return;
    int v = out[i] + bsums[i>>10];
    out[i] = v; cur[i] = v;
    if (i == n-1){ int tot = v + in[i]; out[n]=tot; cur[n]=tot; }
}

// scatter: CSR basis scatter + coarse-edge dedup + winner append + mxD
__global__ void k_scatter(const int* __restrict__ src, const int* __restrict__ dst,
                          const float* __restrict__ ea){
    int e = blockIdx.x*blockDim.x + threadIdx.x;   // Ee % 256 == 0: all lanes live
    float2 f = reinterpret_cast<const float2*>(ea)[e];
    float f0 = fminf(fmaxf(f.x, 0.f), 1.f);
    float f1 = fminf(fmaxf(f.y, 0.f), 1.f);
    int s = src[e], d = dst[e];
    int old = atomicSub(&d_deg[d], 1);
    int p = d_rs[d] + d_bsums[d>>10] + (old - 1);
    d_basF[p] = make_float4(__int_as_float(s),
                            (1.f-f0)*(1.f-f1), f0*(1.f-f1), (1.f-f0)*f1);
    // coarse dedup (cid ready from k_prep; pp normalized by k_cellpp)
    int cs = d_cid[s], cd = d_cid[d];
    bool win = false;
    float m = 0.f;
    if (cs != cd){
        int b = cs / Gn;
        int key = b*Gn*Gn + (cs - b*Gn)*Gn + (cd - b*Gn);
        unsigned bit = 1u << (key & 31);
        unsigned oldb = atomicOr(&d_markb[key >> 5], bit);
        if (!(oldb & bit)){
            win = true;
            float cx = d_pp[2*cs]   - d_pp[2*cd];
            float cy = d_pp[2*cs+1] - d_pp[2*cd+1];
            m = fmaxf(fabsf(cx), fabsf(cy));
        }
    }
    unsigned wmask = __ballot_sync(0xFFFFFFFFu, win);
    float wm = m;
    #pragma unroll
    for (int o = 16; o; o >>= 1) wm = fmaxf(wm, __shfl_xor_sync(0xFFFFFFFFu, wm, o));
    int lane = threadIdx.x & 31;
    int nwin = __popc(wmask);
    int base = 0;
    if (lane == 0 && nwin){
        base = atomicAdd(&d_EcD[0], nwin);
        atomicMax(&d_mxD[0], __float_as_uint(wm));
    }
    base = __shfl_sync(0xFFFFFFFFu, base, 0);
    if (win){
        int i = base + __popc(wmask & ((1u << lane) - 1));
        d_csrc[i] = cs; d_cdst[i] = cd;
        atomicAdd(&d_degc[cd], 1);
    }
}

// ---------- BN stats tail ----------
__device__ __forceinline__ void bn_stats_tail(const float* g, const float* b,
                                              int layer, int cout, float denom, int useTw){
    __shared__ float part[2][128];
    __shared__ float tot[128];
    int t = threadIdx.x;
    int idx = t & 127, grp = t >> 7;
    float S = 0.f;
    for (int k = grp; k < NCPY; k += 2) S += __ldcg(&d_bnaccM[layer][k][idx]);
    part[grp][idx] = S;
    __syncthreads();
    if (t < 128) tot[t] = part[0][t] + part[1][t];
    __syncthreads();
    if (t < cout){
        float dn = useTw ? __ldcg(&d_twD[0]) : denom;
        float m = tot[t]/dn;
        float v = tot[64+t]/dn - m*m;
        float a = g[t]*rsqrtf(v + EPSn);
        d_ssbL[layer][t]    = a;
        d_ssbL[layer][32+t] = b[t] - m*a;
    }
}

// ---------------- fused fine layer ----------------
template<int CINH, int COUT, bool RESID, bool SUMS, bool POOL>
__global__ void k_fuse2(const __half* __restrict__ X1, const __half* __restrict__ X2,
                        const float* __restrict__ W, __half* __restrict__ uout,
                        const int* __restrict__ rs, const int* __restrict__ bs,
                        const float4* __restrict__ basF,
                        int layer, int wcin, int ab1, int ab2,
                        const float* __restrict__ g, const float* __restrict__ bb_){
    constexpr int CPL  = CINH/8;
    constexpr int NOUT = COUT/8;
    __shared__ float Wsh[4*CINH*COUT];
    __shared__ float A1s[32], B1s[32], A2s[32];
    __shared__ float As[8][4][4][CINH];
    __shared__ float sv[8][32][NOUT];
    __shared__ int   isLast;
    int tid = threadIdx.x;
    for (int idx = tid; idx < 4*wcin*COUT; idx += 256) Wsh[idx] = W[idx];
    if (tid < 32){
        A1s[tid] = (ab1 >= 0) ? d_ssbL[ab1][tid]    : 1.f;
        float b1 = (ab1 >= 0) ? d_ssbL[ab1][32+tid] : 0.f;
        A2s[tid] = (ab2 >= 0) ? d_ssbL[ab2][tid]    : 0.f;
        float b2 = (ab2 >= 0) ? d_ssbL[ab2][32+tid] : 0.f;
        B1s[tid] = b1 + b2;
    }
    __syncthreads();
    int w = tid >> 5, lane = tid & 31;
    int sub = lane >> 3, il = lane & 7;
    int d = (blockIdx.x*8 + w)*4 + sub;
    int beg = rs[d]   + bs[d>>10];
    int end = rs[d+1] + bs[(d+1)>>10];

    float a0[CPL], a1[CPL], a2[CPL], am[CPL];
    float e0[CPL], e1[CPL], e2[CPL], em[CPL];
    float k0=0.f, k1=0.f, k2=0.f;
    #pragma unroll
    for (int cc=0;cc<CPL;cc++){
        a0[cc]=a1[cc]=a2[cc]=am[cc]=0.f;
        e0[cc]=e1[cc]=e2[cc]=em[cc]=0.f;
    }
    const __half2* X1h = reinterpret_cast<const __half2*>(X1);
    const __half2* X2h = reinterpret_cast<const __half2*>(X2);

    #pragma unroll 2
    for (int p = beg; p < end; p++){
        float4 q = __ldg(&basF[p]);
        int sa = __float_as_int(q.x);
        if (SUMS){ k0 += q.y; k1 += q.z; k2 += q.w; }
        if (CPL == 2){
            float2 xa = __half22float2(X1h[(size_t)sa*8 + il]);
            am[0] += xa.x;       am[CPL-1] += xa.y;
            a0[0] += q.y*xa.x;   a0[CPL-1] += q.y*xa.y;
            a1[0] += q.z*xa.x;   a1[CPL-1] += q.z*xa.y;
            a2[0] += q.w*xa.x;   a2[CPL-1] += q.w*xa.y;
            if (RESID){
                float2 ya = __half22float2(X2h[(size_t)sa*8 + il]);
                em[0] += ya.x;       em[CPL-1] += ya.y;
                e0[0] += q.y*ya.x;   e0[CPL-1] += q.y*ya.y;
                e1[0] += q.z*ya.x;   e1[CPL-1] += q.z*ya.y;
                e2[0] += q.w*ya.x;   e2[CPL-1] += q.w*ya.y;
            }
        } else {
            float xa = __half2float(X1[(size_t)sa*8 + il]);
            am[0] += xa;
            a0[0] += q.y*xa; a1[0] += q.z*xa; a2[0] += q.w*xa;
        }
    }

    float s0, s1, s2;
    if (SUMS){
        s0 = k0; s1 = k1; s2 = k2;
        if (il == 0) d_S4[d] = make_float4(s0, s1, s2, 0.f);
    } else {
        float4 S = __ldg(&d_S4[d]);
        s0 = S.x; s1 = S.y; s2 = S.z;
    }
    float fdeg = (float)(end - beg);
    float s3 = fdeg - s0 - s1 - s2;

    #pragma unroll
    for (int cc=0;cc<CPL;cc++){
        int ch = il*CPL + cc;
        float av1 = A1s[ch], av2 = A2s[ch], bbv = B1s[ch];
        float a3 = am[cc] - a0[cc] - a1[cc] - a2[cc];
        float r0 = av1*a0[cc] + bbv*s0;
        float r1 = av1*a1[cc] + bbv*s1;
        float r2 = av1*a2[cc] + bbv*s2;
        float r3 = av1*a3     + bbv*s3;
        if (RESID){
            float ee3 = em[cc] - e0[cc] - e1[cc] - e2[cc];
            r0 += av2*e0[cc]; r1 += av2*e1[cc]; r2 += av2*e2[cc]; r3 += av2*ee3;
        }
        As[w][sub][0][ch] = r0;
        As[w][sub][1][ch] = r1;
        As[w][sub][2][ch] = r2;
        As[w][sub][3][ch] = r3;
    }
    __syncwarp();
    int dg = end - beg; if (dg < 1) dg = 1;
    float inv = 1.f / (float)dg;
    int cidd = POOL ? d_cid[d] : 0;
    #pragma unroll
    for (int q=0;q<NOUT;q++){
        int ch = (lane & 7) + 8*q;
        float v = 0.f;
        for (int k=0;k<4;k++){
            const float* ak = &As[w][sub][k][0];
            const float* wk = &Wsh[k*wcin*COUT + ch];
            for (int i=0;i<wcin;i++) v += ak[i] * wk[i*COUT];
        }
        v *= inv;
        v = (v > 0.f) ? v : expm1f(v);
        if (POOL){
            atomicMax(&d_xpe[cidd*32 + ch], encf(v));   // pre-BN max (a5>0 ⇒ argmax invariant)
        } else {
            uout[(size_t)d*COUT + ch] = __float2half(v);
        }
        sv[w][lane][q] = v;
    }
    __syncthreads();
    if (w == 0 && lane < COUT){
        float S = 0.f, Q = 0.f;
        int cl = lane & 7, q = lane >> 3;
        #pragma unroll
        for (int j=0;j<8;j++){
            #pragma unroll
            for (int s2i=0;s2i<4;s2i++){
                float v = sv[j][s2i*8 + cl][q];
                S += v; Q += v*v;
            }
        }
        int cp = blockIdx.x & (NCPY-1);
        atomicAdd(&d_bnaccM[layer][cp][lane],    S);
        atomicAdd(&d_bnaccM[layer][cp][64+lane], Q);
    }
    __threadfence();
    __syncthreads();
    if (tid == 0) isLast = (atomicAdd(&d_tickL[layer],1) == (int)gridDim.x-1);
    __syncthreads();
    if (isLast) bn_stats_tail(g, bb_, layer, COUT, (float)Nn, 0);
}

// ---------------- fused coarse layer: block per dst ----------------
__global__ void k_fuseC(const __half* __restrict__ X1, const float* __restrict__ W,
                        __half* __restrict__ uout, const int* __restrict__ rs,
                        const float4* __restrict__ basF, int layer, int ab1, int sums,
                        const float* __restrict__ g, const float* __restrict__ bb_){
    __shared__ float Wsh[4*32*32];
    __shared__ float A1s[32], B1s[32];
    __shared__ float accS[8][4][32];
    __shared__ float sKS[8][4];
    __shared__ float Afin[4][32];
    __shared__ float sks[4];
    __shared__ int   isLast;
    int d = blockIdx.x, tid = threadIdx.x;
    int w = tid >> 5, lane = tid & 31;
    for (int idx = tid; idx < 4096; idx += 256) Wsh[idx] = W[idx];
    if (tid < 32){
        A1s[tid] = (ab1 >= 0) ? d_ssbL[ab1][tid]    : 1.f;
        B1s[tid] = (ab1 >= 0) ? d_ssbL[ab1][32+tid] : 0.f;
    }
    __syncthreads();
    int beg = rs[d], end = rs[d+1];
    float a0=0,a1=0,a2=0,am=0, k0=0,k1=0,k2=0;
    #pragma unroll 2
    for (int p = beg + w; p < end; p += 8){
        float4 q = __ldg(&basF[p]);
        int s = __float_as_int(q.x);
        float xv = __half2float(X1[(size_t)s*32 + lane]);
        am += xv;
        a0 += q.y*xv; a1 += q.z*xv; a2 += q.w*xv;
        if (sums){ k0 += q.y; k1 += q.z; k2 += q.w; }
    }
    accS[w][0][lane]=a0; accS[w][1][lane]=a1; accS[w][2][lane]=a2; accS[w][3][lane]=am;
    if (lane == 0){ sKS[w][0]=k0; sKS[w][1]=k1; sKS[w][2]=k2; }
    __syncthreads();
    if (tid < 128){
        int k = tid >> 5, i = tid & 31;
        float r = 0.f;
        #pragma unroll
        for (int j = 0; j < 8; j++) r += accS[j][k][i];
        Afin[k][i] = r;
    }
    if (tid >= 128 && tid < 131 && sums){
        int k = tid - 128;
        float r = 0.f;
        #pragma unroll
        for (int j = 0; j < 8; j++) r += sKS[j][k];
        sks[k] = r;
    }
    __syncthreads();
    if (w == 0){
        float s0, s1, s2;
        if (sums){
            s0 = sks[0]; s1 = sks[1]; s2 = sks[2];
            if (lane == 0) d_S4C[d] = make_float4(s0, s1, s2, 0.f);
        } else {
            float4 S = __ldg(&d_S4C[d]);
            s0 = S.x; s1 = S.y; s2 = S.z;
        }
        float fdeg = (float)(end - beg);
        float s3 = fdeg - s0 - s1 - s2;
        int i = lane;
        float r0 = Afin[0][i], r1 = Afin[1][i], r2 = Afin[2][i];
        float r3 = Afin[3][i] - r0 - r1 - r2;
        Afin[0][i] = A1s[i]*r0 + B1s[i]*s0;
        Afin[1][i] = A1s[i]*r1 + B1s[i]*s1;
        Afin[2][i] = A1s[i]*r2 + B1s[i]*s2;
        Afin[3][i] = A1s[i]*r3 + B1s[i]*s3;
        __syncwarp();
        float v = 0.f;
        #pragma unroll
        for (int k = 0; k < 4; k++)
            for (int i2 = 0; i2 < 32; i2++)
                v += Afin[k][i2] * Wsh[(k*32+i2)*32 + lane];
        int dg = end - beg; if (dg < 1) dg = 1;
        v /= (float)dg;
        v = (v > 0.f) ? v : expm1f(v);
        uout[(size_t)d*32 + lane] = __float2half(v);
        float ww = d_wv[d];
        int cp = blockIdx.x & (NCPY-1);
        atomicAdd(&d_bnaccM[layer][cp][lane],    ww*v);
        atomicAdd(&d_bnaccM[layer][cp][64+lane], ww*v*v);
    }
    __threadfence();
    __syncthreads();
    if (tid == 0) isLast = (atomicAdd(&d_tickL[layer],1) == (int)gridDim.x-1);
    __syncthreads();
    if (isLast) bn_stats_tail(g, bb_, layer, 32, 0.f, 1);
}

// ---------------- pool finish: apply BN5 affine to cell maxima ----------------
__global__ void k_poolfin(){
    int idx = blockIdx.x*blockDim.x + threadIdx.x;
    if (idx >= Sn*32) return;
    int s = idx >> 5, c = idx & 31;
    float v = 0.f;
    if (d_ccnt[s] > 0)
        v = d_ssbL[5][c]*decf(d_xpe[idx]) + d_ssbL[5][32+c];
    d_xph[idx] = __float2half(v);
}

__global__ void k_scatterC(){
    int i = blockIdx.x*blockDim.x + threadIdx.x;
    if (i >= d_EcD[0]) return;
    int cs = d_csrc[i], cd = d_cdst[i];
    int p = atomicAdd(&d_curc[cd], 1);
    float mx = __uint_as_float(d_mxD[0]);
    float den = 2.f*mx + 1e-12f;
    float f0 = (d_pp[2*cs]   - d_pp[2*cd])   / den + 0.5f;
    float f1 = (d_pp[2*cs+1] - d_pp[2*cd+1]) / den + 0.5f;
    f0 = fminf(fmaxf(f0, 0.f), 1.f);
    f1 = fminf(fmaxf(f1, 0.f), 1.f);
    d_basFC[p] = make_float4(__int_as_float(cs),
                             (1.f-f0)*(1.f-f1), f0*(1.f-f1), (1.f-f0)*f1);
}

// ---------------- final ----------------
__global__ void k_final(const __half* __restrict__ h, const float* __restrict__ fcW,
                        float* __restrict__ out){
    __shared__ float ss[8][33];
    __shared__ float sw8[8];
    __shared__ float gm[32];
    __shared__ float swv;
    int b = blockIdx.x;
    int lane = threadIdx.x & 31, w = threadIdx.x >> 5;
    float a7 = d_ssbL[7][lane], b7 = d_ssbL[7][32+lane];
    float acc = 0.f, accw = 0.f;
    for (int s = b*Gn + w; s < (b+1)*Gn; s += 8){
        float ww = d_wv[s];
        acc  += ww * (a7*__half2float(h[(size_t)s*32 + lane]) + b7);
        accw += ww;
    }
    ss[w][lane] = acc;
    if (lane == 0) sw8[w] = accw;
    __syncthreads();
    if (threadIdx.x < 32){
        float S = 0.f;
        #pragma unroll
        for (int j=0;j<8;j++) S += ss[j][threadIdx.x];
        gm[threadIdx.x] = S;
    }
    if (threadIdx.x == 0){
        float W = 0.f;
        #pragma unroll
        for (int j=0;j<8;j++) W += sw8[j];
        swv = W;
    }
    __syncthreads();
    if (threadIdx.x < 10){
        float o = 0.f;
        #pragma unroll
        for (int c=0;c<32;c++) o += (gm[c]/swv) * fcW[c*10 + threadIdx.x];
        out[b*10 + threadIdx.x] = o;
    }
}

// ---------------- epilogue: restore scratch for next graph replay -------------
__global__ void k_epi(){
    int i = blockIdx.x*blockDim.x + threadIdx.x;
    int st = gridDim.x*blockDim.x;
    for (int j=i; j<MARKW; j+=st) d_markb[j]=0u;
    for (int j=i; j<Sn;    j+=st){ d_ccnt[j]=0; d_degc[j]=0; }
    for (int j=i; j<Sn*2;  j+=st) d_pp[j]=0.f;
    for (int j=i; j<Sn*32; j+=st) d_xpe[j]=0u;
    float* bm = &d_bnaccM[0][0][0];
    for (int j=i; j<8*NCPY*128; j+=st) bm[j]=0.f;
    if (i < 2) d_tickS[i]=0;
    if (i < 8) d_tickL[i]=0;
    if (i==0){ d_EcD[0]=0; d_mxD[0]=0u; d_twD[0]=0.f; }
}

// ---------------- host ----------------
template <typename T>
static T* devptr(const void* sym){
    void* p = nullptr;
    cudaGetSymbolAddress(&p, sym);
    return (T*)p;
}

extern "C" void kernel_launch(void* const* d_in, const int* in_sizes, int n_in,
                              void* d_out, int out_size){
    const float* x     = (const float*)d_in[0];
    const float* pos   = (const float*)d_in[1];
    const int*   batch = (const int*)  d_in[2];
    const int*   ei    = (const int*)  d_in[3];
    const int*   src   = ei;
    const int*   dst   = ei + Ee;
    const float* ea    = (const float*)d_in[4];
    const float* fcW   = (const float*)d_in[29];
    float* out = (float*)d_out;

    __half* pH0  = devptr<__half>(d_H0);
    __half* pHa  = devptr<__half>(d_Ha);
    __half* pHb  = devptr<__half>(d_Hb);
    __half* pHc  = devptr<__half>(d_Hc);
    __half* pxph = devptr<__half>(d_xph);
    __half* pCh0 = devptr<__half>(d_Ch0);
    __half* pCh1 = devptr<__half>(d_Ch1);
    int*    pdeg  = devptr<int>(d_deg);
    int*    prs   = devptr<int>(d_rs);
    int*    pbs   = devptr<int>(d_bsums);
    int*    pbsC  = devptr<int>(d_bsumsC);
    float4* pbf   = devptr<float4>(d_basF);
    int*    pdegc = devptr<int>(d_degc);
    int*    prsc  = devptr<int>(d_rsc);
    int*    pcurc = devptr<int>(d_curc);
    float4* pbfC  = devptr<float4>(d_basFC);
    int*    ptick = devptr<int>(d_tickS);

    // prolog + coarse graph build (dedup fused into scatter)
    k_prep<<<Ee/256,256>>>(dst, pos, batch, x);
    k_cellpp<<<(Sn+255)/256,256>>>();
    k_scan12<<<256,1024>>>(pdeg, prs, Nn, ptick, pbs);
    k_scatter<<<Ee/256,256>>>(src, dst, ea);
    k_scan12<<<8,1024>>>(pdegc, prsc, Sn, ptick+1, pbsC);     // separate bsums!
    k_scan3<<<(Sn+255)/256,256>>>(pdegc, prsc, pcurc, Sn, pbsC);
    k_scatterC<<<Ee/256,256>>>();

    // fine layers; l0 computes basis sums; l5 pools inline (no Ha store)
    k_fuse2<16, 8,false,true ,false><<<Nn/32,256>>>(pH0, nullptr, (const float*)d_in[5],  pHa, prs, pbs, pbf, 0, 10, -1, -1, (const float*)d_in[6],  (const float*)d_in[7]);
    k_fuse2< 8,16,false,false,false><<<Nn/32,256>>>(pHa, nullptr, (const float*)d_in[8],  pHb, prs, pbs, pbf, 1,  8,  0, -1, (const float*)d_in[9],  (const float*)d_in[10]);
    k_fuse2<16,16,false,false,false><<<Nn/32,256>>>(pHb, nullptr, (const float*)d_in[11], pHc, prs, pbs, pbf, 2, 16,  1, -1, (const float*)d_in[12], (const float*)d_in[13]);
    k_fuse2<16,16,false,false,false><<<Nn/32,256>>>(pHc, nullptr, (const float*)d_in[14], pHa, prs, pbs, pbf, 3, 16,  2, -1, (const float*)d_in[15], (const float*)d_in[16]);
    k_fuse2<16,16,false,false,false><<<Nn/32,256>>>(pHa, nullptr, (const float*)d_in[17], pHb, prs, pbs, pbf, 4, 16,  3, -1, (const float*)d_in[18], (const float*)d_in[19]);
    k_fuse2<16,32,true ,false,true ><<<Nn/32,256>>>(pHb, pHc,     (const float*)d_in[20], pHa, prs, pbs, pbf, 5, 16,  4,  2, (const float*)d_in[21], (const float*)d_in[22]);

    // finish pooling (BN5 affine on maxima), then coarse layers
    k_poolfin<<<(Sn*32+255)/256,256>>>();
    k_fuseC<<<Sn,256>>>(pxph, (const float*)d_in[23], pCh0, prsc, pbfC, 6, -1, 1, (const float*)d_in[24], (const float*)d_in[25]);
    k_fuseC<<<Sn,256>>>(pCh0, (const float*)d_in[26], pCh1, prsc, pbfC, 7,  6, 0, (const float*)d_in[27], (const float*)d_in[28]);

    k_final<<<Bn,256>>>(pCh1, fcW, out);

    // epilogue: restore zeroed scratch for the next replay
    k_epi<<<512,256>>>();
    (void)in_sizes; (void)n_in; (void)out_size;
}